// round 5
// baseline (speedup 1.0000x reference)
#include <cuda_runtime.h>

#define OMEGA 1.7f

// packed fp32x2 FMA: d = a*b + d (elementwise on two packed floats)
#define FFMA2(d, a, b) asm("fma.rn.f32x2 %0, %1, %2, %0;" : "+l"(d) : "l"(a), "l"(b))
typedef unsigned long long ull;

// -------- global scratch (allocations are forbidden) --------
__device__ float g_Mop[64 * 256];
__device__ float g_h1[4096 * 512];
__device__ float g_h2[4096 * 512];
__device__ float g_y0[4096 * 256];

// =====================================================================
// setup: G = A A^T (64x64), K = inv(G) via Gauss-Jordan, Mop = K @ A
// =====================================================================
#define SETUP_SMEM ((64 * 260 + 64 * 130) * 4)

__global__ void setup_kernel(const float* __restrict__ A) {
    extern __shared__ float sm[];
    float* As = sm;              // [64][260] staged A
    float* G  = sm + 64 * 260;   // [64][130] augmented [G | I]
    __shared__ float colp[64];
    const int tid = threadIdx.x;

    for (int i = tid; i < 64 * 64; i += 256) {
        int m = i >> 6, d = (i & 63) << 2;
        *(float4*)(As + m * 260 + d) = *(const float4*)(A + m * 256 + d);
    }
    __syncthreads();

    for (int o = tid; o < 64 * 64; o += 256) {
        int i = o >> 6, j = o & 63;
        const float4* ai = (const float4*)(As + i * 260);
        const float4* aj = (const float4*)(As + j * 260);
        float s = 0.f;
        #pragma unroll 8
        for (int d4 = 0; d4 < 64; d4++) {
            float4 a = ai[d4], b = aj[d4];
            s += a.x * b.x + a.y * b.y + a.z * b.z + a.w * b.w;
        }
        G[i * 130 + j] = s;
        G[i * 130 + 64 + j] = (i == j) ? 1.f : 0.f;
    }
    __syncthreads();

    for (int p = 0; p < 64; p++) {
        float pinv = 1.f / G[p * 130 + p];
        if (tid < 64) colp[tid] = G[tid * 130 + p];
        __syncthreads();
        if (tid < 128) G[p * 130 + tid] *= pinv;
        __syncthreads();
        for (int e = tid; e < 64 * 128; e += 256) {
            int i = e >> 7, c = e & 127;
            if (i != p) G[i * 130 + c] -= colp[i] * G[p * 130 + c];
        }
        __syncthreads();
    }

    for (int o = tid; o < 64 * 256; o += 256) {
        int m = o >> 8, d = o & 255;
        float s = 0.f;
        #pragma unroll 8
        for (int j = 0; j < 64; j++) s += G[m * 130 + 64 + j] * As[j * 260 + d];
        g_Mop[o] = s;
    }
}

// =====================================================================
// trunk GEMM: C = act(Amat @ Bmat + bias), BM=128 BN=64 BK=16, 256 thr
// FFMA2 inner loop: B packed over n-pairs, A splat via mov.b64
// =====================================================================
template <bool RELU>
__global__ void gemm_bias(const float* __restrict__ Am, const float* __restrict__ Bm,
                          const float* __restrict__ bias, float* __restrict__ C,
                          int M, int N, int K) {
    __shared__ float As[16][132];
    __shared__ float Bs[16][68];
    const int tid = threadIdx.x;
    const int bm = blockIdx.y * 128, bn = blockIdx.x * 64;
    const int tx = tid & 15, ty = tid >> 4;

    ull acc[8][2];
    #pragma unroll
    for (int i = 0; i < 8; i++) { acc[i][0] = 0ull; acc[i][1] = 0ull; }

    const int ar = tid >> 2, akc = (tid & 3) << 2;
    const int bkr = tid >> 4, bnc = (tid & 15) << 2;

    for (int k0 = 0; k0 < K; k0 += 16) {
        #pragma unroll
        for (int rr = 0; rr < 2; rr++) {
            int r = ar + rr * 64;
            float4 v = *(const float4*)(Am + (size_t)(bm + r) * K + k0 + akc);
            As[akc + 0][r] = v.x; As[akc + 1][r] = v.y;
            As[akc + 2][r] = v.z; As[akc + 3][r] = v.w;
        }
        *(float4*)(&Bs[bkr][bnc]) = *(const float4*)(Bm + (size_t)(k0 + bkr) * N + bn + bnc);
        __syncthreads();

        #pragma unroll
        for (int kk = 0; kk < 16; kk++) {
            ull b0 = *(const ull*)(&Bs[kk][tx * 4]);
            ull b1 = *(const ull*)(&Bs[kk][tx * 4 + 2]);
            #pragma unroll
            for (int i = 0; i < 8; i++) {
                float a = As[kk][ty * 8 + i];
                ull av;
                asm("mov.b64 %0, {%1, %1};" : "=l"(av) : "f"(a));
                FFMA2(acc[i][0], av, b0);
                FFMA2(acc[i][1], av, b1);
            }
        }
        __syncthreads();
    }

    float4 bv = *(const float4*)(bias + bn + tx * 4);
    #pragma unroll
    for (int i = 0; i < 8; i++) {
        float2 lo = *(float2*)&acc[i][0];
        float2 hi = *(float2*)&acc[i][1];
        float4 o;
        o.x = lo.x + bv.x; o.y = lo.y + bv.y;
        o.z = hi.x + bv.z; o.w = hi.y + bv.w;
        if (RELU) {
            o.x = fmaxf(o.x, 0.f); o.y = fmaxf(o.y, 0.f);
            o.z = fmaxf(o.z, 0.f); o.w = fmaxf(o.w, 0.f);
        }
        *(float4*)(C + (size_t)(bm + ty * 8 + i) * N + bn + tx * 4) = o;
    }
}

// =====================================================================
// iteration kernel: persistent 32-row tile, 512 threads (16 warps),
// f32x2-packed LDS.128 GEMM phases
//   tphase: warp = (rg 0..7 -> 4 rows, half -> m = 32*half + lane)
//   yphase: warp = (rg 0..7 -> 4 rows, half -> cols half*128 + j*32 + lane)
//   SMEM: Asm[64][260] A row-major, MoT[256][68] Mop^T,
//         zs[32][260], rv[32][260], ts[32][68]
// =====================================================================
#define ITER_SMEM ((64 * 260 + 256 * 68 + 32 * 260 + 32 * 260 + 32 * 68) * 4)

// ts[r][m] = 0.5 * sum_d zs[r][d] * A[m][d]
__device__ __forceinline__ void tphase(const float* __restrict__ zs,
                                       const float* __restrict__ Asm,
                                       float* __restrict__ ts,
                                       int rg, int half, int lane) {
    const int m = half * 32 + lane;
    const float* ap = Asm + m * 260;
    const float* zp = zs + rg * 4 * 260;
    ull acc[4][2];
    #pragma unroll
    for (int i = 0; i < 4; i++) { acc[i][0] = 0ull; acc[i][1] = 0ull; }
    #pragma unroll 4
    for (int d = 0; d < 256; d += 4) {
        ulonglong2 av = *(const ulonglong2*)(ap + d);
        #pragma unroll
        for (int i = 0; i < 4; i++) {
            ulonglong2 zv = *(const ulonglong2*)(zp + i * 260 + d);
            FFMA2(acc[i][0], zv.x, av.x);
            FFMA2(acc[i][1], zv.y, av.y);
        }
    }
    #pragma unroll
    for (int i = 0; i < 4; i++) {
        float2 f0 = *(float2*)&acc[i][0];
        float2 f1 = *(float2*)&acc[i][1];
        ts[(rg * 4 + i) * 68 + m] = 0.5f * ((f0.x + f0.y) + (f1.x + f1.y));
    }
}

// s[i][j] = sum_m ts[r][m] * MoT[c][m],  c = half*128 + j*32 + lane
__device__ __forceinline__ void yphase(const float* __restrict__ ts,
                                       const float* __restrict__ MoT,
                                       int rg, int half, int lane, float s[4][4]) {
    const float* tp = ts + rg * 4 * 68;
    const float* mp = MoT + (half * 128 + lane) * 68;
    ull acc[4][4];
    #pragma unroll
    for (int i = 0; i < 4; i++)
        #pragma unroll
        for (int j = 0; j < 4; j++) acc[i][j] = 0ull;
    #pragma unroll 2
    for (int m = 0; m < 64; m += 4) {
        ulonglong2 tv[4], bv[4];
        #pragma unroll
        for (int i = 0; i < 4; i++) tv[i] = *(const ulonglong2*)(tp + i * 68 + m);
        #pragma unroll
        for (int j = 0; j < 4; j++) bv[j] = *(const ulonglong2*)(mp + j * 32 * 68 + m);
        #pragma unroll
        for (int i = 0; i < 4; i++)
            #pragma unroll
            for (int j = 0; j < 4; j++) {
                FFMA2(acc[i][j], tv[i].x, bv[j].x);
                FFMA2(acc[i][j], tv[i].y, bv[j].y);
            }
    }
    #pragma unroll
    for (int i = 0; i < 4; i++)
        #pragma unroll
        for (int j = 0; j < 4; j++) {
            float2 f = *(float2*)&acc[i][j];
            s[i][j] = f.x + f.y;
        }
}

__global__ __launch_bounds__(512, 1) void iter_kernel(
    const float* __restrict__ y0g, const float* __restrict__ bcong,
    const float* __restrict__ Ag, float* __restrict__ outg,
    const int* __restrict__ nip) {
    extern __shared__ float sm[];
    float* Asm = sm;               // [64][260]
    float* MoT = Asm + 64 * 260;   // [256][68]
    float* zs  = MoT + 256 * 68;   // [32][260]
    float* rv  = zs + 32 * 260;    // [32][260]
    float* ts  = rv + 32 * 260;    // [32][68]
    const int tid = threadIdx.x;
    const int lane = tid & 31, w = tid >> 5;
    const int rg = w & 7, half = w >> 3;
    const int row0 = blockIdx.x * 32;
    const int ni = *nip;

    for (int i = tid; i < 64 * 64; i += 512) {
        int m = i >> 6, d = (i & 63) << 2;
        *(float4*)(Asm + m * 260 + d) = *(const float4*)(Ag + m * 256 + d);
    }
    for (int i = tid; i < 64 * 256; i += 512) {
        int m = i >> 8, c = i & 255;
        MoT[c * 68 + m] = g_Mop[i];
    }
    for (int i = tid; i < 32 * 64; i += 512) {
        int r = i >> 6, c = (i & 63) << 2;
        *(float4*)(zs + r * 260 + c) = *(const float4*)(y0g + (size_t)(row0 + r) * 256 + c);
    }
    __syncthreads();

    // rv = 0.5*y0 - (0.5*(y0 @ A^T) - bcon) @ Mop    (zs == y0 here)
    tphase(zs, Asm, ts, rg, half, lane);
    {
        int m = half * 32 + lane;
        #pragma unroll
        for (int i = 0; i < 4; i++)
            ts[(rg * 4 + i) * 68 + m] -= bcong[(size_t)(row0 + rg * 4 + i) * 64 + m];
    }
    __syncthreads();
    {
        float s[4][4];
        yphase(ts, MoT, rg, half, lane, s);
        #pragma unroll
        for (int i = 0; i < 4; i++) {
            int r = rg * 4 + i;
            #pragma unroll
            for (int j = 0; j < 4; j++) {
                int c = half * 128 + j * 32 + lane;
                rv[r * 260 + c] = 0.5f * zs[r * 260 + c] - s[i][j];
            }
        }
    }
    __syncthreads();

    for (int it = 0; it < ni; it++) {
        tphase(zs, Asm, ts, rg, half, lane);
        __syncthreads();
        float s[4][4];
        yphase(ts, MoT, rg, half, lane, s);
        if (it == ni - 1) {
            #pragma unroll
            for (int i = 0; i < 4; i++) {
                int r = rg * 4 + i;
                #pragma unroll
                for (int j = 0; j < 4; j++) {
                    int c = half * 128 + j * 32 + lane;
                    float y = 0.5f * zs[r * 260 + c] - s[i][j] + rv[r * 260 + c];
                    outg[(size_t)(row0 + r) * 256 + c] = y;
                }
            }
        } else {
            #pragma unroll
            for (int i = 0; i < 4; i++) {
                int r = rg * 4 + i;
                #pragma unroll
                for (int j = 0; j < 4; j++) {
                    int c = half * 128 + j * 32 + lane;
                    float z = zs[r * 260 + c];
                    float y = 0.5f * z - s[i][j] + rv[r * 260 + c];
                    float wv = fmaxf(2.f * y - z, 0.f);
                    zs[r * 260 + c] = z + OMEGA * (wv - y);
                }
            }
            __syncthreads();
        }
    }
}

// =====================================================================
extern "C" void kernel_launch(void* const* d_in, const int* in_sizes, int n_in,
                              void* d_out, int out_size) {
    const float* x    = (const float*)d_in[0];
    const float* bcon = (const float*)d_in[1];
    const float* A    = (const float*)d_in[2];
    const float* W1   = (const float*)d_in[3];
    const float* b1   = (const float*)d_in[4];
    const float* W2   = (const float*)d_in[5];
    const float* b2   = (const float*)d_in[6];
    const float* W3   = (const float*)d_in[7];
    const float* b3   = (const float*)d_in[8];
    const float* Wout = (const float*)d_in[9];
    const float* bout = (const float*)d_in[10];
    const int*   nip  = (const int*)d_in[11];
    float* out = (float*)d_out;

    cudaFuncSetAttribute(setup_kernel, cudaFuncAttributeMaxDynamicSharedMemorySize, SETUP_SMEM);
    cudaFuncSetAttribute(iter_kernel,  cudaFuncAttributeMaxDynamicSharedMemorySize, ITER_SMEM);

    void *ph1, *ph2, *py0;
    cudaGetSymbolAddress(&ph1, g_h1);
    cudaGetSymbolAddress(&ph2, g_h2);
    cudaGetSymbolAddress(&py0, g_y0);
    float* h1 = (float*)ph1;
    float* h2 = (float*)ph2;
    float* y0 = (float*)py0;

    setup_kernel<<<1, 256, SETUP_SMEM>>>(A);
    gemm_bias<true ><<<dim3(8, 32), 256>>>(x,  W1, b1, h1, 4096, 512, 128);
    gemm_bias<true ><<<dim3(8, 32), 256>>>(h1, W2, b2, h2, 4096, 512, 512);
    gemm_bias<true ><<<dim3(8, 32), 256>>>(h2, W3, b3, h1, 4096, 512, 512);
    gemm_bias<false><<<dim3(4, 32), 256>>>(h1, Wout, bout, y0, 4096, 256, 512);
    iter_kernel<<<128, 512, ITER_SMEM>>>(y0, bcon, A, out, nip);
}

// round 6
// speedup vs baseline: 1.2276x; 1.2276x over previous
#include <cuda_runtime.h>

#define OMEGA 1.7f

// packed fp32x2 FMA: d = a*b + d
#define FFMA2(d, a, b) asm("fma.rn.f32x2 %0, %1, %2, %0;" : "+l"(d) : "l"(a), "l"(b))
#define SPLAT2(d, s)   asm("mov.b64 %0, {%1, %1};" : "=l"(d) : "f"(s))
typedef unsigned long long ull;

// -------- global scratch (allocations are forbidden) --------
__device__ float g_Mop[64 * 256];
__device__ float g_h1[4096 * 512];
__device__ float g_h2[4096 * 512];
__device__ float g_y0[4096 * 256];

// =====================================================================
// setup: G = A A^T (64x64), K = inv(G) via Gauss-Jordan, Mop = K @ A
// =====================================================================
#define SETUP_SMEM ((64 * 260 + 64 * 130) * 4)

__global__ void setup_kernel(const float* __restrict__ A) {
    extern __shared__ float sm[];
    float* As = sm;              // [64][260]
    float* G  = sm + 64 * 260;   // [64][130] augmented [G | I]
    __shared__ float colp[64];
    const int tid = threadIdx.x;

    for (int i = tid; i < 64 * 64; i += 256) {
        int m = i >> 6, d = (i & 63) << 2;
        *(float4*)(As + m * 260 + d) = *(const float4*)(A + m * 256 + d);
    }
    __syncthreads();

    for (int o = tid; o < 64 * 64; o += 256) {
        int i = o >> 6, j = o & 63;
        const float4* ai = (const float4*)(As + i * 260);
        const float4* aj = (const float4*)(As + j * 260);
        float s = 0.f;
        #pragma unroll 8
        for (int d4 = 0; d4 < 64; d4++) {
            float4 a = ai[d4], b = aj[d4];
            s += a.x * b.x + a.y * b.y + a.z * b.z + a.w * b.w;
        }
        G[i * 130 + j] = s;
        G[i * 130 + 64 + j] = (i == j) ? 1.f : 0.f;
    }
    __syncthreads();

    for (int p = 0; p < 64; p++) {
        float pinv = 1.f / G[p * 130 + p];
        if (tid < 64) colp[tid] = G[tid * 130 + p];
        __syncthreads();
        if (tid < 128) G[p * 130 + tid] *= pinv;
        __syncthreads();
        for (int e = tid; e < 64 * 128; e += 256) {
            int i = e >> 7, c = e & 127;
            if (i != p) G[i * 130 + c] -= colp[i] * G[p * 130 + c];
        }
        __syncthreads();
    }

    for (int o = tid; o < 64 * 256; o += 256) {
        int m = o >> 8, d = o & 255;
        float s = 0.f;
        #pragma unroll 8
        for (int j = 0; j < 64; j++) s += G[m * 130 + 64 + j] * As[j * 260 + d];
        g_Mop[o] = s;
    }
}

// =====================================================================
// trunk GEMM v2: C = act(A@B + bias), BM=128 BN=128 BK=16, 256 thr,
// 8x8 per thread, FFMA2, double-buffered smem w/ register prefetch
// =====================================================================
template <bool RELU>
__global__ __launch_bounds__(256, 1) void gemm_bias_v2(
    const float* __restrict__ Am, const float* __restrict__ Bm,
    const float* __restrict__ bias, float* __restrict__ C,
    int M, int N, int K) {
    __shared__ float As[2][16][132];   // k-major: As[buf][k][m]
    __shared__ float Bs[2][16][136];   // Bs[buf][k][n]
    const int tid = threadIdx.x;
    const int bm = blockIdx.y * 128, bn = blockIdx.x * 128;
    const int tx = tid & 15, ty = tid >> 4;

    const int arow = tid >> 1, akc = (tid & 1) * 8;
    const int bkr = tid >> 4, bnc = (tid & 15) * 8;

    const float* ag = Am + (size_t)(bm + arow) * K + akc;
    const float* bg = Bm + (size_t)bkr * N + bn + bnc;

    ull acc[8][4];
    #pragma unroll
    for (int i = 0; i < 8; i++)
        #pragma unroll
        for (int j = 0; j < 4; j++) acc[i][j] = 0ull;

    // preload block 0
    float4 pa0 = *(const float4*)(ag);
    float4 pa1 = *(const float4*)(ag + 4);
    float4 pb0 = *(const float4*)(bg);
    float4 pb1 = *(const float4*)(bg + 4);
    {
        float av[8] = {pa0.x, pa0.y, pa0.z, pa0.w, pa1.x, pa1.y, pa1.z, pa1.w};
        #pragma unroll
        for (int l = 0; l < 8; l++) As[0][akc + l][arow] = av[l];
        *(float4*)(&Bs[0][bkr][bnc]) = pb0;
        *(float4*)(&Bs[0][bkr][bnc + 4]) = pb1;
    }
    __syncthreads();

    const int nblk = K / 16;
    for (int blk = 0; blk < nblk; blk++) {
        int buf = blk & 1;
        if (blk + 1 < nblk) {
            const float* agn = ag + (blk + 1) * 16;
            const float* bgn = bg + (size_t)(blk + 1) * 16 * N;
            pa0 = *(const float4*)(agn);
            pa1 = *(const float4*)(agn + 4);
            pb0 = *(const float4*)(bgn);
            pb1 = *(const float4*)(bgn + 4);
        }

        #pragma unroll
        for (int kk = 0; kk < 16; kk++) {
            float4 af0 = *(const float4*)(&As[buf][kk][ty * 8]);
            float4 af1 = *(const float4*)(&As[buf][kk][ty * 8 + 4]);
            ulonglong2 bq0 = *(const ulonglong2*)(&Bs[buf][kk][tx * 8]);
            ulonglong2 bq1 = *(const ulonglong2*)(&Bs[buf][kk][tx * 8 + 4]);
            float a[8] = {af0.x, af0.y, af0.z, af0.w, af1.x, af1.y, af1.z, af1.w};
            #pragma unroll
            for (int i = 0; i < 8; i++) {
                ull av; SPLAT2(av, a[i]);
                FFMA2(acc[i][0], av, bq0.x);
                FFMA2(acc[i][1], av, bq0.y);
                FFMA2(acc[i][2], av, bq1.x);
                FFMA2(acc[i][3], av, bq1.y);
            }
        }

        if (blk + 1 < nblk) {
            int nb = buf ^ 1;
            float av[8] = {pa0.x, pa0.y, pa0.z, pa0.w, pa1.x, pa1.y, pa1.z, pa1.w};
            #pragma unroll
            for (int l = 0; l < 8; l++) As[nb][akc + l][arow] = av[l];
            *(float4*)(&Bs[nb][bkr][bnc]) = pb0;
            *(float4*)(&Bs[nb][bkr][bnc + 4]) = pb1;
        }
        __syncthreads();
    }

    float4 bv0 = *(const float4*)(bias + bn + tx * 8);
    float4 bv1 = *(const float4*)(bias + bn + tx * 8 + 4);
    #pragma unroll
    for (int i = 0; i < 8; i++) {
        float2 c0 = *(float2*)&acc[i][0];
        float2 c1 = *(float2*)&acc[i][1];
        float2 c2 = *(float2*)&acc[i][2];
        float2 c3 = *(float2*)&acc[i][3];
        float4 o0, o1;
        o0.x = c0.x + bv0.x; o0.y = c0.y + bv0.y;
        o0.z = c1.x + bv0.z; o0.w = c1.y + bv0.w;
        o1.x = c2.x + bv1.x; o1.y = c2.y + bv1.y;
        o1.z = c3.x + bv1.z; o1.w = c3.y + bv1.w;
        if (RELU) {
            o0.x = fmaxf(o0.x, 0.f); o0.y = fmaxf(o0.y, 0.f);
            o0.z = fmaxf(o0.z, 0.f); o0.w = fmaxf(o0.w, 0.f);
            o1.x = fmaxf(o1.x, 0.f); o1.y = fmaxf(o1.y, 0.f);
            o1.z = fmaxf(o1.z, 0.f); o1.w = fmaxf(o1.w, 0.f);
        }
        float* cp = C + (size_t)(bm + ty * 8 + i) * N + bn + tx * 8;
        *(float4*)(cp) = o0;
        *(float4*)(cp + 4) = o1;
    }
}

// =====================================================================
// iteration kernel (R3 version): persistent 32-row tile, 256 threads,
// warp-private rows, f32x2-packed
// =====================================================================
#define ITER_SMEM ((64 * 258 + 256 * 66 + 32 * 260 + 32 * 260 + 32 * 66) * 4)

__device__ __forceinline__ void tphase(const float* __restrict__ zs,
                                       const float* __restrict__ Asm,
                                       float* __restrict__ ts, int rg, int lane) {
    ull acc[4][2];
    #pragma unroll
    for (int i = 0; i < 4; i++) { acc[i][0] = 0ull; acc[i][1] = 0ull; }
    const float* zp0 = zs + rg * 4 * 260;
    const float* a0 = Asm + lane * 258;
    const float* a1 = Asm + (lane + 32) * 258;
    #pragma unroll 4
    for (int d = 0; d < 256; d += 2) {
        ull ap0 = *(const ull*)(a0 + d);
        ull ap1 = *(const ull*)(a1 + d);
        #pragma unroll
        for (int i = 0; i < 4; i++) {
            ull zp = *(const ull*)(zp0 + i * 260 + d);
            FFMA2(acc[i][0], zp, ap0);
            FFMA2(acc[i][1], zp, ap1);
        }
    }
    #pragma unroll
    for (int i = 0; i < 4; i++) {
        float2 f0 = *(float2*)&acc[i][0];
        float2 f1 = *(float2*)&acc[i][1];
        ts[(rg * 4 + i) * 66 + lane]      = 0.5f * (f0.x + f0.y);
        ts[(rg * 4 + i) * 66 + lane + 32] = 0.5f * (f1.x + f1.y);
    }
}

__device__ __forceinline__ void yphase(const float* __restrict__ ts,
                                       const float* __restrict__ MoT,
                                       int rg, int lane, float s[4][8]) {
    ull acc[4][8];
    #pragma unroll
    for (int i = 0; i < 4; i++)
        #pragma unroll
        for (int j = 0; j < 8; j++) acc[i][j] = 0ull;
    const float* tp = ts + rg * 4 * 66;
    const float* mp = MoT + lane * 66;
    #pragma unroll 2
    for (int m = 0; m < 64; m += 2) {
        ull a[4], b[8];
        #pragma unroll
        for (int i = 0; i < 4; i++) a[i] = *(const ull*)(tp + i * 66 + m);
        #pragma unroll
        for (int j = 0; j < 8; j++) b[j] = *(const ull*)(mp + j * 32 * 66 + m);
        #pragma unroll
        for (int i = 0; i < 4; i++)
            #pragma unroll
            for (int j = 0; j < 8; j++) FFMA2(acc[i][j], a[i], b[j]);
    }
    #pragma unroll
    for (int i = 0; i < 4; i++)
        #pragma unroll
        for (int j = 0; j < 8; j++) {
            float2 f = *(float2*)&acc[i][j];
            s[i][j] = f.x + f.y;
        }
}

__global__ __launch_bounds__(256, 1) void iter_kernel(
    const float* __restrict__ y0g, const float* __restrict__ bcong,
    const float* __restrict__ Ag, float* __restrict__ outg,
    const int* __restrict__ nip) {
    extern __shared__ float sm[];
    float* Asm = sm;               // [64][258]
    float* MoT = Asm + 64 * 258;   // [256][66]
    float* zs  = MoT + 256 * 66;   // [32][260]
    float* rv  = zs + 32 * 260;    // [32][260]
    float* ts  = rv + 32 * 260;    // [32][66]
    const int tid = threadIdx.x;
    const int lane = tid & 31, rg = tid >> 5;
    const int row0 = blockIdx.x * 32;
    const int ni = *nip;

    for (int i = tid; i < 64 * 128; i += 256) {
        int m = i >> 7, d = (i & 127) << 1;
        *(float2*)(Asm + m * 258 + d) = *(const float2*)(Ag + m * 256 + d);
    }
    for (int i = tid; i < 64 * 256; i += 256) {
        int m = i >> 8, c = i & 255;
        MoT[c * 66 + m] = g_Mop[i];
    }
    for (int i = tid; i < 32 * 64; i += 256) {
        int r = i >> 6, c = (i & 63) << 2;
        *(float4*)(zs + r * 260 + c) = *(const float4*)(y0g + (size_t)(row0 + r) * 256 + c);
    }
    __syncthreads();

    tphase(zs, Asm, ts, rg, lane);
    #pragma unroll
    for (int i = 0; i < 4; i++) {
        int r = rg * 4 + i;
        ts[r * 66 + lane]      -= bcong[(size_t)(row0 + r) * 64 + lane];
        ts[r * 66 + lane + 32] -= bcong[(size_t)(row0 + r) * 64 + lane + 32];
    }
    __syncwarp();
    {
        float s[4][8];
        yphase(ts, MoT, rg, lane, s);
        #pragma unroll
        for (int i = 0; i < 4; i++) {
            int r = rg * 4 + i;
            #pragma unroll
            for (int j = 0; j < 8; j++) {
                int c = lane + 32 * j;
                rv[r * 260 + c] = 0.5f * zs[r * 260 + c] - s[i][j];
            }
        }
    }
    __syncwarp();

    for (int it = 0; it < ni; it++) {
        tphase(zs, Asm, ts, rg, lane);
        __syncwarp();
        float s[4][8];
        yphase(ts, MoT, rg, lane, s);
        if (it == ni - 1) {
            #pragma unroll
            for (int i = 0; i < 4; i++) {
                int r = rg * 4 + i;
                #pragma unroll
                for (int j = 0; j < 8; j++) {
                    int c = lane + 32 * j;
                    float y = 0.5f * zs[r * 260 + c] - s[i][j] + rv[r * 260 + c];
                    outg[(size_t)(row0 + r) * 256 + c] = y;
                }
            }
        } else {
            #pragma unroll
            for (int i = 0; i < 4; i++) {
                int r = rg * 4 + i;
                #pragma unroll
                for (int j = 0; j < 8; j++) {
                    int c = lane + 32 * j;
                    float z = zs[r * 260 + c];
                    float y = 0.5f * z - s[i][j] + rv[r * 260 + c];
                    float w = fmaxf(2.f * y - z, 0.f);
                    zs[r * 260 + c] = z + OMEGA * (w - y);
                }
            }
            __syncwarp();
        }
    }
}

// =====================================================================
extern "C" void kernel_launch(void* const* d_in, const int* in_sizes, int n_in,
                              void* d_out, int out_size) {
    const float* x    = (const float*)d_in[0];
    const float* bcon = (const float*)d_in[1];
    const float* A    = (const float*)d_in[2];
    const float* W1   = (const float*)d_in[3];
    const float* b1   = (const float*)d_in[4];
    const float* W2   = (const float*)d_in[5];
    const float* b2   = (const float*)d_in[6];
    const float* W3   = (const float*)d_in[7];
    const float* b3   = (const float*)d_in[8];
    const float* Wout = (const float*)d_in[9];
    const float* bout = (const float*)d_in[10];
    const int*   nip  = (const int*)d_in[11];
    float* out = (float*)d_out;

    cudaFuncSetAttribute(setup_kernel, cudaFuncAttributeMaxDynamicSharedMemorySize, SETUP_SMEM);
    cudaFuncSetAttribute(iter_kernel,  cudaFuncAttributeMaxDynamicSharedMemorySize, ITER_SMEM);

    void *ph1, *ph2, *py0;
    cudaGetSymbolAddress(&ph1, g_h1);
    cudaGetSymbolAddress(&ph2, g_h2);
    cudaGetSymbolAddress(&py0, g_y0);
    float* h1 = (float*)ph1;
    float* h2 = (float*)ph2;
    float* y0 = (float*)py0;

    setup_kernel<<<1, 256, SETUP_SMEM>>>(A);
    gemm_bias_v2<true ><<<dim3(4, 32), 256>>>(x,  W1, b1, h1, 4096, 512, 128);
    gemm_bias_v2<true ><<<dim3(4, 32), 256>>>(h1, W2, b2, h2, 4096, 512, 512);
    gemm_bias_v2<true ><<<dim3(4, 32), 256>>>(h2, W3, b3, h1, 4096, 512, 512);
    gemm_bias_v2<false><<<dim3(2, 32), 256>>>(h1, Wout, bout, y0, 4096, 256, 512);
    iter_kernel<<<128, 256, ITER_SMEM>>>(y0, bcon, A, out, nip);
}

// round 7
// speedup vs baseline: 1.2726x; 1.0366x over previous
#include <cuda_runtime.h>

#define OMEGA 1.7f

// packed fp32x2 FMA: d = a*b + d
#define FFMA2(d, a, b) asm("fma.rn.f32x2 %0, %1, %2, %0;" : "+l"(d) : "l"(a), "l"(b))
#define SPLAT2(d, s)   asm("mov.b64 %0, {%1, %1};" : "=l"(d) : "f"(s))
typedef unsigned long long ull;

// -------- global scratch (allocations are forbidden) --------
__device__ float g_Mop[64 * 256];
__device__ float g_h1[4096 * 512];
__device__ float g_h2[4096 * 512];
__device__ float g_y0[4096 * 256];

// =====================================================================
// setup: G = A A^T (64x64), K = inv(G) via Gauss-Jordan, Mop = K @ A
// =====================================================================
#define SETUP_SMEM ((64 * 260 + 64 * 130) * 4)

__global__ void setup_kernel(const float* __restrict__ A) {
    extern __shared__ float sm[];
    float* As = sm;              // [64][260]
    float* G  = sm + 64 * 260;   // [64][130] augmented [G | I]
    __shared__ float colp[64];
    const int tid = threadIdx.x;

    for (int i = tid; i < 64 * 64; i += 256) {
        int m = i >> 6, d = (i & 63) << 2;
        *(float4*)(As + m * 260 + d) = *(const float4*)(A + m * 256 + d);
    }
    __syncthreads();

    for (int o = tid; o < 64 * 64; o += 256) {
        int i = o >> 6, j = o & 63;
        const float4* ai = (const float4*)(As + i * 260);
        const float4* aj = (const float4*)(As + j * 260);
        float s = 0.f;
        #pragma unroll 8
        for (int d4 = 0; d4 < 64; d4++) {
            float4 a = ai[d4], b = aj[d4];
            s += a.x * b.x + a.y * b.y + a.z * b.z + a.w * b.w;
        }
        G[i * 130 + j] = s;
        G[i * 130 + 64 + j] = (i == j) ? 1.f : 0.f;
    }
    __syncthreads();

    for (int p = 0; p < 64; p++) {
        float pinv = 1.f / G[p * 130 + p];
        if (tid < 64) colp[tid] = G[tid * 130 + p];
        __syncthreads();
        if (tid < 128) G[p * 130 + tid] *= pinv;
        __syncthreads();
        for (int e = tid; e < 64 * 128; e += 256) {
            int i = e >> 7, c = e & 127;
            if (i != p) G[i * 130 + c] -= colp[i] * G[p * 130 + c];
        }
        __syncthreads();
    }

    for (int o = tid; o < 64 * 256; o += 256) {
        int m = o >> 8, d = o & 255;
        float s = 0.f;
        #pragma unroll 8
        for (int j = 0; j < 64; j++) s += G[m * 130 + 64 + j] * As[j * 260 + d];
        g_Mop[o] = s;
    }
}

// =====================================================================
// trunk GEMM v3: C = act(A@B + bias), BM=128 BN=128 BK=16, 512 threads
// per-thread 8x4 (warp = 8 rows, lane = 4 cols), FFMA2,
// double-buffered smem with register prefetch
// =====================================================================
template <bool RELU>
__global__ __launch_bounds__(512, 1) void gemm_bias_v3(
    const float* __restrict__ Am, const float* __restrict__ Bm,
    const float* __restrict__ bias, float* __restrict__ C,
    int M, int N, int K) {
    __shared__ float As[2][16][132];   // k-major: As[buf][k][m]
    __shared__ float Bs[2][16][132];   // Bs[buf][k][n]
    const int tid = threadIdx.x;
    const int lane = tid & 31, wid = tid >> 5;   // wid 0..15 = rowgroup
    const int bm = blockIdx.y * 128, bn = blockIdx.x * 128;

    // staging assignments
    const int arow = tid >> 2, akc = (tid & 3) * 4;   // A: 128 rows x 16 k, float4
    const int bkr = tid >> 5, bnc = (tid & 31) * 4;   // B: 16 k x 128 n, float4

    const float* ag = Am + (size_t)(bm + arow) * K + akc;
    const float* bg = Bm + (size_t)bkr * N + bn + bnc;

    ull acc[8][2];
    #pragma unroll
    for (int i = 0; i < 8; i++) { acc[i][0] = 0ull; acc[i][1] = 0ull; }

    // preload block 0
    float4 pa = *(const float4*)(ag);
    float4 pb = *(const float4*)(bg);
    As[0][akc + 0][arow] = pa.x;
    As[0][akc + 1][arow] = pa.y;
    As[0][akc + 2][arow] = pa.z;
    As[0][akc + 3][arow] = pa.w;
    *(float4*)(&Bs[0][bkr][bnc]) = pb;
    __syncthreads();

    const int nblk = K / 16;
    for (int blk = 0; blk < nblk; blk++) {
        int buf = blk & 1;
        if (blk + 1 < nblk) {
            pa = *(const float4*)(ag + (blk + 1) * 16);
            pb = *(const float4*)(bg + (size_t)(blk + 1) * 16 * N);
        }

        #pragma unroll
        for (int kk = 0; kk < 16; kk++) {
            float4 af0 = *(const float4*)(&As[buf][kk][wid * 8]);
            float4 af1 = *(const float4*)(&As[buf][kk][wid * 8 + 4]);
            ulonglong2 bq = *(const ulonglong2*)(&Bs[buf][kk][lane * 4]);
            float a[8] = {af0.x, af0.y, af0.z, af0.w, af1.x, af1.y, af1.z, af1.w};
            #pragma unroll
            for (int i = 0; i < 8; i++) {
                ull av; SPLAT2(av, a[i]);
                FFMA2(acc[i][0], av, bq.x);
                FFMA2(acc[i][1], av, bq.y);
            }
        }

        if (blk + 1 < nblk) {
            int nb = buf ^ 1;
            As[nb][akc + 0][arow] = pa.x;
            As[nb][akc + 1][arow] = pa.y;
            As[nb][akc + 2][arow] = pa.z;
            As[nb][akc + 3][arow] = pa.w;
            *(float4*)(&Bs[nb][bkr][bnc]) = pb;
        }
        __syncthreads();
    }

    float4 bv = *(const float4*)(bias + bn + lane * 4);
    #pragma unroll
    for (int i = 0; i < 8; i++) {
        float2 c0 = *(float2*)&acc[i][0];
        float2 c1 = *(float2*)&acc[i][1];
        float4 o;
        o.x = c0.x + bv.x; o.y = c0.y + bv.y;
        o.z = c1.x + bv.z; o.w = c1.y + bv.w;
        if (RELU) {
            o.x = fmaxf(o.x, 0.f); o.y = fmaxf(o.y, 0.f);
            o.z = fmaxf(o.z, 0.f); o.w = fmaxf(o.w, 0.f);
        }
        *(float4*)(C + (size_t)(bm + wid * 8 + i) * N + bn + lane * 4) = o;
    }
}

// =====================================================================
// iteration kernel (R3 version): persistent 32-row tile, 256 threads,
// warp-private rows, f32x2-packed
// =====================================================================
#define ITER_SMEM ((64 * 258 + 256 * 66 + 32 * 260 + 32 * 260 + 32 * 66) * 4)

__device__ __forceinline__ void tphase(const float* __restrict__ zs,
                                       const float* __restrict__ Asm,
                                       float* __restrict__ ts, int rg, int lane) {
    ull acc[4][2];
    #pragma unroll
    for (int i = 0; i < 4; i++) { acc[i][0] = 0ull; acc[i][1] = 0ull; }
    const float* zp0 = zs + rg * 4 * 260;
    const float* a0 = Asm + lane * 258;
    const float* a1 = Asm + (lane + 32) * 258;
    #pragma unroll 4
    for (int d = 0; d < 256; d += 2) {
        ull ap0 = *(const ull*)(a0 + d);
        ull ap1 = *(const ull*)(a1 + d);
        #pragma unroll
        for (int i = 0; i < 4; i++) {
            ull zp = *(const ull*)(zp0 + i * 260 + d);
            FFMA2(acc[i][0], zp, ap0);
            FFMA2(acc[i][1], zp, ap1);
        }
    }
    #pragma unroll
    for (int i = 0; i < 4; i++) {
        float2 f0 = *(float2*)&acc[i][0];
        float2 f1 = *(float2*)&acc[i][1];
        ts[(rg * 4 + i) * 66 + lane]      = 0.5f * (f0.x + f0.y);
        ts[(rg * 4 + i) * 66 + lane + 32] = 0.5f * (f1.x + f1.y);
    }
}

__device__ __forceinline__ void yphase(const float* __restrict__ ts,
                                       const float* __restrict__ MoT,
                                       int rg, int lane, float s[4][8]) {
    ull acc[4][8];
    #pragma unroll
    for (int i = 0; i < 4; i++)
        #pragma unroll
        for (int j = 0; j < 8; j++) acc[i][j] = 0ull;
    const float* tp = ts + rg * 4 * 66;
    const float* mp = MoT + lane * 66;
    #pragma unroll 2
    for (int m = 0; m < 64; m += 2) {
        ull a[4], b[8];
        #pragma unroll
        for (int i = 0; i < 4; i++) a[i] = *(const ull*)(tp + i * 66 + m);
        #pragma unroll
        for (int j = 0; j < 8; j++) b[j] = *(const ull*)(mp + j * 32 * 66 + m);
        #pragma unroll
        for (int i = 0; i < 4; i++)
            #pragma unroll
            for (int j = 0; j < 8; j++) FFMA2(acc[i][j], a[i], b[j]);
    }
    #pragma unroll
    for (int i = 0; i < 4; i++)
        #pragma unroll
        for (int j = 0; j < 8; j++) {
            float2 f = *(float2*)&acc[i][j];
            s[i][j] = f.x + f.y;
        }
}

__global__ __launch_bounds__(256, 1) void iter_kernel(
    const float* __restrict__ y0g, const float* __restrict__ bcong,
    const float* __restrict__ Ag, float* __restrict__ outg,
    const int* __restrict__ nip) {
    extern __shared__ float sm[];
    float* Asm = sm;               // [64][258]
    float* MoT = Asm + 64 * 258;   // [256][66]
    float* zs  = MoT + 256 * 66;   // [32][260]
    float* rv  = zs + 32 * 260;    // [32][260]
    float* ts  = rv + 32 * 260;    // [32][66]
    const int tid = threadIdx.x;
    const int lane = tid & 31, rg = tid >> 5;
    const int row0 = blockIdx.x * 32;
    const int ni = *nip;

    for (int i = tid; i < 64 * 128; i += 256) {
        int m = i >> 7, d = (i & 127) << 1;
        *(float2*)(Asm + m * 258 + d) = *(const float2*)(Ag + m * 256 + d);
    }
    for (int i = tid; i < 64 * 256; i += 256) {
        int m = i >> 8, c = i & 255;
        MoT[c * 66 + m] = g_Mop[i];
    }
    for (int i = tid; i < 32 * 64; i += 256) {
        int r = i >> 6, c = (i & 63) << 2;
        *(float4*)(zs + r * 260 + c) = *(const float4*)(y0g + (size_t)(row0 + r) * 256 + c);
    }
    __syncthreads();

    tphase(zs, Asm, ts, rg, lane);
    #pragma unroll
    for (int i = 0; i < 4; i++) {
        int r = rg * 4 + i;
        ts[r * 66 + lane]      -= bcong[(size_t)(row0 + r) * 64 + lane];
        ts[r * 66 + lane + 32] -= bcong[(size_t)(row0 + r) * 64 + lane + 32];
    }
    __syncwarp();
    {
        float s[4][8];
        yphase(ts, MoT, rg, lane, s);
        #pragma unroll
        for (int i = 0; i < 4; i++) {
            int r = rg * 4 + i;
            #pragma unroll
            for (int j = 0; j < 8; j++) {
                int c = lane + 32 * j;
                rv[r * 260 + c] = 0.5f * zs[r * 260 + c] - s[i][j];
            }
        }
    }
    __syncwarp();

    for (int it = 0; it < ni; it++) {
        tphase(zs, Asm, ts, rg, lane);
        __syncwarp();
        float s[4][8];
        yphase(ts, MoT, rg, lane, s);
        if (it == ni - 1) {
            #pragma unroll
            for (int i = 0; i < 4; i++) {
                int r = rg * 4 + i;
                #pragma unroll
                for (int j = 0; j < 8; j++) {
                    int c = lane + 32 * j;
                    float y = 0.5f * zs[r * 260 + c] - s[i][j] + rv[r * 260 + c];
                    outg[(size_t)(row0 + r) * 256 + c] = y;
                }
            }
        } else {
            #pragma unroll
            for (int i = 0; i < 4; i++) {
                int r = rg * 4 + i;
                #pragma unroll
                for (int j = 0; j < 8; j++) {
                    int c = lane + 32 * j;
                    float z = zs[r * 260 + c];
                    float y = 0.5f * z - s[i][j] + rv[r * 260 + c];
                    float w = fmaxf(2.f * y - z, 0.f);
                    zs[r * 260 + c] = z + OMEGA * (w - y);
                }
            }
            __syncwarp();
        }
    }
}

// =====================================================================
extern "C" void kernel_launch(void* const* d_in, const int* in_sizes, int n_in,
                              void* d_out, int out_size) {
    const float* x    = (const float*)d_in[0];
    const float* bcon = (const float*)d_in[1];
    const float* A    = (const float*)d_in[2];
    const float* W1   = (const float*)d_in[3];
    const float* b1   = (const float*)d_in[4];
    const float* W2   = (const float*)d_in[5];
    const float* b2   = (const float*)d_in[6];
    const float* W3   = (const float*)d_in[7];
    const float* b3   = (const float*)d_in[8];
    const float* Wout = (const float*)d_in[9];
    const float* bout = (const float*)d_in[10];
    const int*   nip  = (const int*)d_in[11];
    float* out = (float*)d_out;

    cudaFuncSetAttribute(setup_kernel, cudaFuncAttributeMaxDynamicSharedMemorySize, SETUP_SMEM);
    cudaFuncSetAttribute(iter_kernel,  cudaFuncAttributeMaxDynamicSharedMemorySize, ITER_SMEM);

    void *ph1, *ph2, *py0;
    cudaGetSymbolAddress(&ph1, g_h1);
    cudaGetSymbolAddress(&ph2, g_h2);
    cudaGetSymbolAddress(&py0, g_y0);
    float* h1 = (float*)ph1;
    float* h2 = (float*)ph2;
    float* y0 = (float*)py0;

    setup_kernel<<<1, 256, SETUP_SMEM>>>(A);
    gemm_bias_v3<true ><<<dim3(4, 32), 512>>>(x,  W1, b1, h1, 4096, 512, 128);
    gemm_bias_v3<true ><<<dim3(4, 32), 512>>>(h1, W2, b2, h2, 4096, 512, 512);
    gemm_bias_v3<true ><<<dim3(4, 32), 512>>>(h2, W3, b3, h1, 4096, 512, 512);
    gemm_bias_v3<false><<<dim3(2, 32), 512>>>(h1, Wout, bout, y0, 4096, 256, 512);
    iter_kernel<<<128, 256, ITER_SMEM>>>(y0, bcon, A, out, nip);
}

// round 12
// speedup vs baseline: 1.3188x; 1.0363x over previous
#include <cuda_runtime.h>
#include <cuda_bf16.h>
#include <cstdint>
#include <mma.h>

using namespace nvcuda;

#define OMEGA 1.7f
#define FFMA2(d, a, b) asm("fma.rn.f32x2 %0, %1, %2, %0;" : "+l"(d) : "l"(a), "l"(b))
typedef unsigned long long ull;

// ---------------- global scratch (allocations are forbidden) ----------------
__device__ float g_Mop[64 * 256];
__device__ float g_y0[4096 * 256];
__device__ __nv_bfloat16 g_xh[4096 * 128],  g_xl[4096 * 128];
__device__ __nv_bfloat16 g_h1h[4096 * 512], g_h1l[4096 * 512];
__device__ __nv_bfloat16 g_h2h[4096 * 512], g_h2l[4096 * 512];
__device__ __nv_bfloat16 g_w1h[128 * 512],  g_w1l[128 * 512];
__device__ __nv_bfloat16 g_w2h[512 * 512],  g_w2l[512 * 512];
__device__ __nv_bfloat16 g_w3h[512 * 512],  g_w3l[512 * 512];
__device__ __nv_bfloat16 g_w4h[512 * 256],  g_w4l[512 * 256];

// ---------------- split converts (elementwise, no transpose) ----------------
__global__ void cvt_split(const float* __restrict__ in, __nv_bfloat16* __restrict__ hi,
                          __nv_bfloat16* __restrict__ lo, int n) {
    int i = blockIdx.x * 256 + threadIdx.x;
    if (i < n) {
        float v = in[i];
        __nv_bfloat16 h = __float2bfloat16(v);
        hi[i] = h;
        lo[i] = __float2bfloat16(v - __bfloat162float(h));
    }
}

// ---------------- setup: Mop = inv(A A^T) @ A ----------------
#define SETUP_SMEM ((64 * 260 + 64 * 130) * 4)
__global__ void setup_kernel(const float* __restrict__ A) {
    extern __shared__ float sm[];
    float* As = sm;
    float* G  = sm + 64 * 260;
    __shared__ float colp[64];
    const int tid = threadIdx.x;
    for (int i = tid; i < 64 * 64; i += 256) {
        int m = i >> 6, d = (i & 63) << 2;
        *(float4*)(As + m * 260 + d) = *(const float4*)(A + m * 256 + d);
    }
    __syncthreads();
    for (int o = tid; o < 64 * 64; o += 256) {
        int i = o >> 6, j = o & 63;
        const float4* ai = (const float4*)(As + i * 260);
        const float4* aj = (const float4*)(As + j * 260);
        float s = 0.f;
        #pragma unroll 8
        for (int d4 = 0; d4 < 64; d4++) {
            float4 a = ai[d4], b = aj[d4];
            s += a.x * b.x + a.y * b.y + a.z * b.z + a.w * b.w;
        }
        G[i * 130 + j] = s;
        G[i * 130 + 64 + j] = (i == j) ? 1.f : 0.f;
    }
    __syncthreads();
    for (int p = 0; p < 64; p++) {
        float pinv = 1.f / G[p * 130 + p];
        if (tid < 64) colp[tid] = G[tid * 130 + p];
        __syncthreads();
        if (tid < 128) G[p * 130 + tid] *= pinv;
        __syncthreads();
        for (int e = tid; e < 64 * 128; e += 256) {
            int i = e >> 7, c = e & 127;
            if (i != p) G[i * 130 + c] -= colp[i] * G[p * 130 + c];
        }
        __syncthreads();
    }
    for (int o = tid; o < 64 * 256; o += 256) {
        int m = o >> 8, d = o & 255;
        float s = 0.f;
        #pragma unroll 8
        for (int j = 0; j < 64; j++) s += G[m * 130 + 64 + j] * As[j * 260 + d];
        g_Mop[o] = s;
    }
}

// ---------------- wmma trunk GEMM (split-bf16, 3 terms) ----------------
// C[BM=128 x BN=64] = act(A @ B + bias);  A [M][K] hi/lo bf16 row-major,
// B [K][N] hi/lo bf16 row-major (native weight layout).
// 8 warps: warp (wr 0..3, wc 0..1) owns 32x32; 2x2 m16n16k16 frags; BK=32.
#define ALD 40   // A smem row stride (bf16)
#define BLD 72   // B smem row stride (bf16)
#define ELD 36   // epilogue f32 row stride

template <bool RELU, bool F32OUT>
__global__ __launch_bounds__(256) void gemm_wmma(
    const __nv_bfloat16* __restrict__ Ah, const __nv_bfloat16* __restrict__ Al,
    const __nv_bfloat16* __restrict__ Bh, const __nv_bfloat16* __restrict__ Bl,
    const float* __restrict__ bias, float* __restrict__ outf,
    __nv_bfloat16* __restrict__ outh, __nv_bfloat16* __restrict__ outl,
    int M, int N, int K) {
    __shared__ char smbuf[36864];
    __shared__ float sbias[64];
    __nv_bfloat16* As_h = (__nv_bfloat16*)smbuf;                  // [128][ALD]
    __nv_bfloat16* As_l = As_h + 128 * ALD;
    __nv_bfloat16* Bs_h = As_l + 128 * ALD;                       // [32][BLD]
    __nv_bfloat16* Bs_l = Bs_h + 32 * BLD;
    float* ep = (float*)smbuf;                                    // epilogue union

    const int tid = threadIdx.x, lane = tid & 31, wid = tid >> 5;
    const int wr = wid & 3, wc = wid >> 2;
    const int bm = blockIdx.y * 128, bn = blockIdx.x * 64;

    if (tid < 64) sbias[tid] = bias[bn + tid];

    wmma::fragment<wmma::accumulator, 16, 16, 16, float> acc[2][2];
    #pragma unroll
    for (int i = 0; i < 2; i++)
        #pragma unroll
        for (int j = 0; j < 2; j++) wmma::fill_fragment(acc[i][j], 0.f);

    const int arow = tid >> 2, aseg = (tid & 3) * 8;   // A: rows arow, arow+64
    const int brow = tid >> 3, bseg = (tid & 7) * 8;   // B: 32 rows x 8 segs

    for (int k0 = 0; k0 < K; k0 += 32) {
        __syncthreads();
        // stage A 128x32 hi+lo: each thread covers rows arow and arow+64
        #pragma unroll
        for (int rr = 0; rr < 2; rr++) {
            int row = arow + rr * 64;
            size_t g = (size_t)(bm + row) * K + k0 + aseg;
            *(uint4*)(As_h + row * ALD + aseg) = *(const uint4*)(Ah + g);
            *(uint4*)(As_l + row * ALD + aseg) = *(const uint4*)(Al + g);
        }
        // stage B 32x64 hi+lo
        {
            size_t g = (size_t)(k0 + brow) * N + bn + bseg;
            *(uint4*)(Bs_h + brow * BLD + bseg) = *(const uint4*)(Bh + g);
            *(uint4*)(Bs_l + brow * BLD + bseg) = *(const uint4*)(Bl + g);
        }
        __syncthreads();

        #pragma unroll
        for (int kk = 0; kk < 32; kk += 16) {
            wmma::fragment<wmma::matrix_a, 16, 16, 16, __nv_bfloat16, wmma::row_major> ah[2], al[2];
            wmma::fragment<wmma::matrix_b, 16, 16, 16, __nv_bfloat16, wmma::row_major> bh[2], bl[2];
            #pragma unroll
            for (int i = 0; i < 2; i++) {
                wmma::load_matrix_sync(ah[i], As_h + (wr * 32 + i * 16) * ALD + kk, ALD);
                wmma::load_matrix_sync(al[i], As_l + (wr * 32 + i * 16) * ALD + kk, ALD);
            }
            #pragma unroll
            for (int j = 0; j < 2; j++) {
                wmma::load_matrix_sync(bh[j], Bs_h + kk * BLD + wc * 32 + j * 16, BLD);
                wmma::load_matrix_sync(bl[j], Bs_l + kk * BLD + wc * 32 + j * 16, BLD);
            }
            #pragma unroll
            for (int i = 0; i < 2; i++)
                #pragma unroll
                for (int j = 0; j < 2; j++) {
                    wmma::mma_sync(acc[i][j], ah[i], bh[j], acc[i][j]);
                    wmma::mma_sync(acc[i][j], ah[i], bl[j], acc[i][j]);
                    wmma::mma_sync(acc[i][j], al[i], bh[j], acc[i][j]);
                }
        }
    }
    __syncthreads();

    // epilogue: each warp stores its 32x32 f32 tile to private smem region
    float* wep = ep + wid * 32 * ELD;
    #pragma unroll
    for (int i = 0; i < 2; i++)
        #pragma unroll
        for (int j = 0; j < 2; j++)
            wmma::store_matrix_sync(wep + i * 16 * ELD + j * 16, acc[i][j], ELD, wmma::mem_row_major);
    __syncwarp();

    const int grow = bm + wr * 32 + lane;
    const int gcol0 = bn + wc * 32;
    if (F32OUT) {
        float* op = outf + (size_t)grow * N + gcol0;
        #pragma unroll
        for (int c = 0; c < 32; c += 4) {
            float4 v = *(float4*)(wep + lane * ELD + c);
            v.x += sbias[wc * 32 + c + 0];
            v.y += sbias[wc * 32 + c + 1];
            v.z += sbias[wc * 32 + c + 2];
            v.w += sbias[wc * 32 + c + 3];
            if (RELU) {
                v.x = fmaxf(v.x, 0.f); v.y = fmaxf(v.y, 0.f);
                v.z = fmaxf(v.z, 0.f); v.w = fmaxf(v.w, 0.f);
            }
            *(float4*)(op + c) = v;
        }
    } else {
        uint32_t hp[16], lp[16];
        #pragma unroll
        for (int c = 0; c < 32; c += 2) {
            float v0 = wep[lane * ELD + c]     + sbias[wc * 32 + c];
            float v1 = wep[lane * ELD + c + 1] + sbias[wc * 32 + c + 1];
            if (RELU) { v0 = fmaxf(v0, 0.f); v1 = fmaxf(v1, 0.f); }
            __nv_bfloat16 h0 = __float2bfloat16(v0), h1 = __float2bfloat16(v1);
            __nv_bfloat16 l0 = __float2bfloat16(v0 - __bfloat162float(h0));
            __nv_bfloat16 l1 = __float2bfloat16(v1 - __bfloat162float(h1));
            hp[c >> 1] = (uint32_t)__bfloat16_as_ushort(h0) | ((uint32_t)__bfloat16_as_ushort(h1) << 16);
            lp[c >> 1] = (uint32_t)__bfloat16_as_ushort(l0) | ((uint32_t)__bfloat16_as_ushort(l1) << 16);
        }
        size_t g = (size_t)grow * N + gcol0;
        *(uint4*)(outh + g)      = make_uint4(hp[0],  hp[1],  hp[2],  hp[3]);
        *(uint4*)(outh + g + 8)  = make_uint4(hp[4],  hp[5],  hp[6],  hp[7]);
        *(uint4*)(outh + g + 16) = make_uint4(hp[8],  hp[9],  hp[10], hp[11]);
        *(uint4*)(outh + g + 24) = make_uint4(hp[12], hp[13], hp[14], hp[15]);
        *(uint4*)(outl + g)      = make_uint4(lp[0],  lp[1],  lp[2],  lp[3]);
        *(uint4*)(outl + g + 8)  = make_uint4(lp[4],  lp[5],  lp[6],  lp[7]);
        *(uint4*)(outl + g + 16) = make_uint4(lp[8],  lp[9],  lp[10], lp[11]);
        *(uint4*)(outl + g + 24) = make_uint4(lp[12], lp[13], lp[14], lp[15]);
    }
}

// ---------------- iteration kernel (unchanged, FFMA2-rt3 floor) ----------------
#define ITER_SMEM ((64 * 258 + 256 * 66 + 32 * 260 + 32 * 260 + 32 * 66) * 4)

__device__ __forceinline__ void tphase(const float* __restrict__ zs,
                                       const float* __restrict__ Asm,
                                       float* __restrict__ ts, int rg, int lane) {
    ull acc[4][2];
    #pragma unroll
    for (int i = 0; i < 4; i++) { acc[i][0] = 0ull; acc[i][1] = 0ull; }
    const float* zp0 = zs + rg * 4 * 260;
    const float* a0 = Asm + lane * 258;
    const float* a1 = Asm + (lane + 32) * 258;
    #pragma unroll 4
    for (int d = 0; d < 256; d += 2) {
        ull ap0 = *(const ull*)(a0 + d);
        ull ap1 = *(const ull*)(a1 + d);
        #pragma unroll
        for (int i = 0; i < 4; i++) {
            ull zp = *(const ull*)(zp0 + i * 260 + d);
            FFMA2(acc[i][0], zp, ap0);
            FFMA2(acc[i][1], zp, ap1);
        }
    }
    #pragma unroll
    for (int i = 0; i < 4; i++) {
        float2 f0 = *(float2*)&acc[i][0];
        float2 f1 = *(float2*)&acc[i][1];
        ts[(rg * 4 + i) * 66 + lane]      = 0.5f * (f0.x + f0.y);
        ts[(rg * 4 + i) * 66 + lane + 32] = 0.5f * (f1.x + f1.y);
    }
}

__device__ __forceinline__ void yphase(const float* __restrict__ ts,
                                       const float* __restrict__ MoT,
                                       int rg, int lane, float s[4][8]) {
    ull acc[4][8];
    #pragma unroll
    for (int i = 0; i < 4; i++)
        #pragma unroll
        for (int j = 0; j < 8; j++) acc[i][j] = 0ull;
    const float* tp = ts + rg * 4 * 66;
    const float* mp = MoT + lane * 66;
    #pragma unroll 2
    for (int m = 0; m < 64; m += 2) {
        ull a[4], b[8];
        #pragma unroll
        for (int i = 0; i < 4; i++) a[i] = *(const ull*)(tp + i * 66 + m);
        #pragma unroll
        for (int j = 0; j < 8; j++) b[j] = *(const ull*)(mp + j * 32 * 66 + m);
        #pragma unroll
        for (int i = 0; i < 4; i++)
            #pragma unroll
            for (int j = 0; j < 8; j++) FFMA2(acc[i][j], a[i], b[j]);
    }
    #pragma unroll
    for (int i = 0; i < 4; i++)
        #pragma unroll
        for (int j = 0; j < 8; j++) {
            float2 f = *(float2*)&acc[i][j];
            s[i][j] = f.x + f.y;
        }
}

__global__ __launch_bounds__(256, 1) void iter_kernel(
    const float* __restrict__ y0g, const float* __restrict__ bcong,
    const float* __restrict__ Ag, float* __restrict__ outg,
    const int* __restrict__ nip) {
    extern __shared__ float sm[];
    float* Asm = sm;
    float* MoT = Asm + 64 * 258;
    float* zs  = MoT + 256 * 66;
    float* rv  = zs + 32 * 260;
    float* ts  = rv + 32 * 260;
    const int tid = threadIdx.x;
    const int lane = tid & 31, rg = tid >> 5;
    const int row0 = blockIdx.x * 32;
    const int ni = *nip;

    for (int i = tid; i < 64 * 128; i += 256) {
        int m = i >> 7, d = (i & 127) << 1;
        *(float2*)(Asm + m * 258 + d) = *(const float2*)(Ag + m * 256 + d);
    }
    for (int i = tid; i < 64 * 256; i += 256) {
        int m = i >> 8, c = i & 255;
        MoT[c * 66 + m] = g_Mop[i];
    }
    for (int i = tid; i < 32 * 64; i += 256) {
        int r = i >> 6, c = (i & 63) << 2;
        *(float4*)(zs + r * 260 + c) = *(const float4*)(y0g + (size_t)(row0 + r) * 256 + c);
    }
    __syncthreads();

    tphase(zs, Asm, ts, rg, lane);
    #pragma unroll
    for (int i = 0; i < 4; i++) {
        int r = rg * 4 + i;
        ts[r * 66 + lane]      -= bcong[(size_t)(row0 + r) * 64 + lane];
        ts[r * 66 + lane + 32] -= bcong[(size_t)(row0 + r) * 64 + lane + 32];
    }
    __syncwarp();
    {
        float s[4][8];
        yphase(ts, MoT, rg, lane, s);
        #pragma unroll
        for (int i = 0; i < 4; i++) {
            int r = rg * 4 + i;
            #pragma unroll
            for (int j = 0; j < 8; j++) {
                int c = lane + 32 * j;
                rv[r * 260 + c] = 0.5f * zs[r * 260 + c] - s[i][j];
            }
        }
    }
    __syncwarp();

    for (int it = 0; it < ni; it++) {
        tphase(zs, Asm, ts, rg, lane);
        __syncwarp();
        float s[4][8];
        yphase(ts, MoT, rg, lane, s);
        if (it == ni - 1) {
            #pragma unroll
            for (int i = 0; i < 4; i++) {
                int r = rg * 4 + i;
                #pragma unroll
                for (int j = 0; j < 8; j++) {
                    int c = lane + 32 * j;
                    float y = 0.5f * zs[r * 260 + c] - s[i][j] + rv[r * 260 + c];
                    outg[(size_t)(row0 + r) * 256 + c] = y;
                }
            }
        } else {
            #pragma unroll
            for (int i = 0; i < 4; i++) {
                int r = rg * 4 + i;
                #pragma unroll
                for (int j = 0; j < 8; j++) {
                    int c = lane + 32 * j;
                    float z = zs[r * 260 + c];
                    float y = 0.5f * z - s[i][j] + rv[r * 260 + c];
                    float w = fmaxf(2.f * y - z, 0.f);
                    zs[r * 260 + c] = z + OMEGA * (w - y);
                }
            }
            __syncwarp();
        }
    }
}

// =====================================================================
extern "C" void kernel_launch(void* const* d_in, const int* in_sizes, int n_in,
                              void* d_out, int out_size) {
    const float* x    = (const float*)d_in[0];
    const float* bcon = (const float*)d_in[1];
    const float* A    = (const float*)d_in[2];
    const float* W1   = (const float*)d_in[3];
    const float* b1   = (const float*)d_in[4];
    const float* W2   = (const float*)d_in[5];
    const float* b2   = (const float*)d_in[6];
    const float* W3   = (const float*)d_in[7];
    const float* b3   = (const float*)d_in[8];
    const float* Wout = (const float*)d_in[9];
    const float* bout = (const float*)d_in[10];
    const int*   nip  = (const int*)d_in[11];
    float* out = (float*)d_out;

    cudaFuncSetAttribute(setup_kernel, cudaFuncAttributeMaxDynamicSharedMemorySize, SETUP_SMEM);
    cudaFuncSetAttribute(iter_kernel,  cudaFuncAttributeMaxDynamicSharedMemorySize, ITER_SMEM);

    void *py0;
    cudaGetSymbolAddress(&py0, g_y0);
    float* y0 = (float*)py0;
    void *pxh, *pxl, *p1h, *p1l, *p2h, *p2l;
    void *pw1h, *pw1l, *pw2h, *pw2l, *pw3h, *pw3l, *pw4h, *pw4l;
    cudaGetSymbolAddress(&pxh, g_xh);   cudaGetSymbolAddress(&pxl, g_xl);
    cudaGetSymbolAddress(&p1h, g_h1h);  cudaGetSymbolAddress(&p1l, g_h1l);
    cudaGetSymbolAddress(&p2h, g_h2h);  cudaGetSymbolAddress(&p2l, g_h2l);
    cudaGetSymbolAddress(&pw1h, g_w1h); cudaGetSymbolAddress(&pw1l, g_w1l);
    cudaGetSymbolAddress(&pw2h, g_w2h); cudaGetSymbolAddress(&pw2l, g_w2l);
    cudaGetSymbolAddress(&pw3h, g_w3h); cudaGetSymbolAddress(&pw3l, g_w3l);
    cudaGetSymbolAddress(&pw4h, g_w4h); cudaGetSymbolAddress(&pw4l, g_w4l);
    __nv_bfloat16 *xh = (__nv_bfloat16*)pxh, *xl = (__nv_bfloat16*)pxl;
    __nv_bfloat16 *h1h = (__nv_bfloat16*)p1h, *h1l = (__nv_bfloat16*)p1l;
    __nv_bfloat16 *h2h = (__nv_bfloat16*)p2h, *h2l = (__nv_bfloat16*)p2l;
    __nv_bfloat16 *w1h = (__nv_bfloat16*)pw1h, *w1l = (__nv_bfloat16*)pw1l;
    __nv_bfloat16 *w2h = (__nv_bfloat16*)pw2h, *w2l = (__nv_bfloat16*)pw2l;
    __nv_bfloat16 *w3h = (__nv_bfloat16*)pw3h, *w3l = (__nv_bfloat16*)pw3l;
    __nv_bfloat16 *w4h = (__nv_bfloat16*)pw4h, *w4l = (__nv_bfloat16*)pw4l;

    cvt_split<<<(4096 * 128 + 255) / 256, 256>>>(x, xh, xl, 4096 * 128);
    cvt_split<<<(128 * 512 + 255) / 256, 256>>>(W1, w1h, w1l, 128 * 512);
    cvt_split<<<(512 * 512 + 255) / 256, 256>>>(W2, w2h, w2l, 512 * 512);
    cvt_split<<<(512 * 512 + 255) / 256, 256>>>(W3, w3h, w3l, 512 * 512);
    cvt_split<<<(512 * 256 + 255) / 256, 256>>>(Wout, w4h, w4l, 512 * 256);
    setup_kernel<<<1, 256, SETUP_SMEM>>>(A);

    gemm_wmma<true, false><<<dim3(8, 32), 256>>>(xh, xl, w1h, w1l, b1, nullptr, h1h, h1l, 4096, 512, 128);
    gemm_wmma<true, false><<<dim3(8, 32), 256>>>(h1h, h1l, w2h, w2l, b2, nullptr, h2h, h2l, 4096, 512, 512);
    gemm_wmma<true, false><<<dim3(8, 32), 256>>>(h2h, h2l, w3h, w3l, b3, nullptr, h1h, h1l, 4096, 512, 512);
    gemm_wmma<false, true><<<dim3(4, 32), 256>>>(h1h, h1l, w4h, w4l, bout, y0, nullptr, nullptr, 4096, 256, 512);

    iter_kernel<<<128, 256, ITER_SMEM>>>(y0, bcon, A, out, nip);
}

// round 13
// speedup vs baseline: 1.6358x; 1.2404x over previous
#include <cuda_runtime.h>
#include <cuda_bf16.h>
#include <cstdint>
#include <mma.h>

using namespace nvcuda;

#define OMEGA 1.7f
typedef unsigned long long ull;

// ---------------- global scratch (allocations are forbidden) ----------------
__device__ float g_Mop[64 * 256];
__device__ float g_y0[4096 * 256];
__device__ __nv_bfloat16 g_xh[4096 * 128],  g_xl[4096 * 128];
__device__ __nv_bfloat16 g_h1h[4096 * 512], g_h1l[4096 * 512];
__device__ __nv_bfloat16 g_h2h[4096 * 512], g_h2l[4096 * 512];
__device__ __nv_bfloat16 g_w1h[128 * 512],  g_w1l[128 * 512];
__device__ __nv_bfloat16 g_w2h[512 * 512],  g_w2l[512 * 512];
__device__ __nv_bfloat16 g_w3h[512 * 512],  g_w3l[512 * 512];
__device__ __nv_bfloat16 g_w4h[512 * 256],  g_w4l[512 * 256];

__device__ __forceinline__ uint32_t pack_bf2(__nv_bfloat16 a, __nv_bfloat16 b) {
    return (uint32_t)__bfloat16_as_ushort(a) | ((uint32_t)__bfloat16_as_ushort(b) << 16);
}

// ---------------- split converts (elementwise, no transpose) ----------------
__global__ void cvt_split(const float* __restrict__ in, __nv_bfloat16* __restrict__ hi,
                          __nv_bfloat16* __restrict__ lo, int n) {
    int i = blockIdx.x * 256 + threadIdx.x;
    if (i < n) {
        float v = in[i];
        __nv_bfloat16 h = __float2bfloat16(v);
        hi[i] = h;
        lo[i] = __float2bfloat16(v - __bfloat162float(h));
    }
}

// ---------------- setup: Mop = inv(A A^T) @ A ----------------
#define SETUP_SMEM ((64 * 260 + 64 * 130) * 4)
__global__ void setup_kernel(const float* __restrict__ A) {
    extern __shared__ float sm[];
    float* As = sm;
    float* G  = sm + 64 * 260;
    __shared__ float colp[64];
    const int tid = threadIdx.x;
    for (int i = tid; i < 64 * 64; i += 256) {
        int m = i >> 6, d = (i & 63) << 2;
        *(float4*)(As + m * 260 + d) = *(const float4*)(A + m * 256 + d);
    }
    __syncthreads();
    for (int o = tid; o < 64 * 64; o += 256) {
        int i = o >> 6, j = o & 63;
        const float4* ai = (const float4*)(As + i * 260);
        const float4* aj = (const float4*)(As + j * 260);
        float s = 0.f;
        #pragma unroll 8
        for (int d4 = 0; d4 < 64; d4++) {
            float4 a = ai[d4], b = aj[d4];
            s += a.x * b.x + a.y * b.y + a.z * b.z + a.w * b.w;
        }
        G[i * 130 + j] = s;
        G[i * 130 + 64 + j] = (i == j) ? 1.f : 0.f;
    }
    __syncthreads();
    for (int p = 0; p < 64; p++) {
        float pinv = 1.f / G[p * 130 + p];
        if (tid < 64) colp[tid] = G[tid * 130 + p];
        __syncthreads();
        if (tid < 128) G[p * 130 + tid] *= pinv;
        __syncthreads();
        for (int e = tid; e < 64 * 128; e += 256) {
            int i = e >> 7, c = e & 127;
            if (i != p) G[i * 130 + c] -= colp[i] * G[p * 130 + c];
        }
        __syncthreads();
    }
    for (int o = tid; o < 64 * 256; o += 256) {
        int m = o >> 8, d = o & 255;
        float s = 0.f;
        #pragma unroll 8
        for (int j = 0; j < 64; j++) s += G[m * 130 + 64 + j] * As[j * 260 + d];
        g_Mop[o] = s;
    }
}

// ---------------- wmma trunk GEMM (split-bf16, 3 terms) -- unchanged ----------------
#define ALD 40
#define BLD 72
#define ELD 36

template <bool RELU, bool F32OUT>
__global__ __launch_bounds__(256) void gemm_wmma(
    const __nv_bfloat16* __restrict__ Ah, const __nv_bfloat16* __restrict__ Al,
    const __nv_bfloat16* __restrict__ Bh, const __nv_bfloat16* __restrict__ Bl,
    const float* __restrict__ bias, float* __restrict__ outf,
    __nv_bfloat16* __restrict__ outh, __nv_bfloat16* __restrict__ outl,
    int M, int N, int K) {
    __shared__ char smbuf[36864];
    __shared__ float sbias[64];
    __nv_bfloat16* As_h = (__nv_bfloat16*)smbuf;
    __nv_bfloat16* As_l = As_h + 128 * ALD;
    __nv_bfloat16* Bs_h = As_l + 128 * ALD;
    __nv_bfloat16* Bs_l = Bs_h + 32 * BLD;
    float* ep = (float*)smbuf;

    const int tid = threadIdx.x, lane = tid & 31, wid = tid >> 5;
    const int wr = wid & 3, wc = wid >> 2;
    const int bm = blockIdx.y * 128, bn = blockIdx.x * 64;

    if (tid < 64) sbias[tid] = bias[bn + tid];

    wmma::fragment<wmma::accumulator, 16, 16, 16, float> acc[2][2];
    #pragma unroll
    for (int i = 0; i < 2; i++)
        #pragma unroll
        for (int j = 0; j < 2; j++) wmma::fill_fragment(acc[i][j], 0.f);

    const int arow = tid >> 2, aseg = (tid & 3) * 8;
    const int brow = tid >> 3, bseg = (tid & 7) * 8;

    for (int k0 = 0; k0 < K; k0 += 32) {
        __syncthreads();
        #pragma unroll
        for (int rr = 0; rr < 2; rr++) {
            int row = arow + rr * 64;
            size_t g = (size_t)(bm + row) * K + k0 + aseg;
            *(uint4*)(As_h + row * ALD + aseg) = *(const uint4*)(Ah + g);
            *(uint4*)(As_l + row * ALD + aseg) = *(const uint4*)(Al + g);
        }
        {
            size_t g = (size_t)(k0 + brow) * N + bn + bseg;
            *(uint4*)(Bs_h + brow * BLD + bseg) = *(const uint4*)(Bh + g);
            *(uint4*)(Bs_l + brow * BLD + bseg) = *(const uint4*)(Bl + g);
        }
        __syncthreads();

        #pragma unroll
        for (int kk = 0; kk < 32; kk += 16) {
            wmma::fragment<wmma::matrix_a, 16, 16, 16, __nv_bfloat16, wmma::row_major> ah[2], al[2];
            wmma::fragment<wmma::matrix_b, 16, 16, 16, __nv_bfloat16, wmma::row_major> bh[2], bl[2];
            #pragma unroll
            for (int i = 0; i < 2; i++) {
                wmma::load_matrix_sync(ah[i], As_h + (wr * 32 + i * 16) * ALD + kk, ALD);
                wmma::load_matrix_sync(al[i], As_l + (wr * 32 + i * 16) * ALD + kk, ALD);
            }
            #pragma unroll
            for (int j = 0; j < 2; j++) {
                wmma::load_matrix_sync(bh[j], Bs_h + kk * BLD + wc * 32 + j * 16, BLD);
                wmma::load_matrix_sync(bl[j], Bs_l + kk * BLD + wc * 32 + j * 16, BLD);
            }
            #pragma unroll
            for (int i = 0; i < 2; i++)
                #pragma unroll
                for (int j = 0; j < 2; j++) {
                    wmma::mma_sync(acc[i][j], ah[i], bh[j], acc[i][j]);
                    wmma::mma_sync(acc[i][j], ah[i], bl[j], acc[i][j]);
                    wmma::mma_sync(acc[i][j], al[i], bh[j], acc[i][j]);
                }
        }
    }
    __syncthreads();

    float* wep = ep + wid * 32 * ELD;
    #pragma unroll
    for (int i = 0; i < 2; i++)
        #pragma unroll
        for (int j = 0; j < 2; j++)
            wmma::store_matrix_sync(wep + i * 16 * ELD + j * 16, acc[i][j], ELD, wmma::mem_row_major);
    __syncwarp();

    const int grow = bm + wr * 32 + lane;
    const int gcol0 = bn + wc * 32;
    if (F32OUT) {
        float* op = outf + (size_t)grow * N + gcol0;
        #pragma unroll
        for (int c = 0; c < 32; c += 4) {
            float4 v = *(float4*)(wep + lane * ELD + c);
            v.x += sbias[wc * 32 + c + 0];
            v.y += sbias[wc * 32 + c + 1];
            v.z += sbias[wc * 32 + c + 2];
            v.w += sbias[wc * 32 + c + 3];
            if (RELU) {
                v.x = fmaxf(v.x, 0.f); v.y = fmaxf(v.y, 0.f);
                v.z = fmaxf(v.z, 0.f); v.w = fmaxf(v.w, 0.f);
            }
            *(float4*)(op + c) = v;
        }
    } else {
        uint32_t hp[16], lp[16];
        #pragma unroll
        for (int c = 0; c < 32; c += 2) {
            float v0 = wep[lane * ELD + c]     + sbias[wc * 32 + c];
            float v1 = wep[lane * ELD + c + 1] + sbias[wc * 32 + c + 1];
            if (RELU) { v0 = fmaxf(v0, 0.f); v1 = fmaxf(v1, 0.f); }
            __nv_bfloat16 h0 = __float2bfloat16(v0), h1 = __float2bfloat16(v1);
            __nv_bfloat16 l0 = __float2bfloat16(v0 - __bfloat162float(h0));
            __nv_bfloat16 l1 = __float2bfloat16(v1 - __bfloat162float(h1));
            hp[c >> 1] = pack_bf2(h0, h1);
            lp[c >> 1] = pack_bf2(l0, l1);
        }
        size_t g = (size_t)grow * N + gcol0;
        *(uint4*)(outh + g)      = make_uint4(hp[0],  hp[1],  hp[2],  hp[3]);
        *(uint4*)(outh + g + 8)  = make_uint4(hp[4],  hp[5],  hp[6],  hp[7]);
        *(uint4*)(outh + g + 16) = make_uint4(hp[8],  hp[9],  hp[10], hp[11]);
        *(uint4*)(outh + g + 24) = make_uint4(hp[12], hp[13], hp[14], hp[15]);
        *(uint4*)(outl + g)      = make_uint4(lp[0],  lp[1],  lp[2],  lp[3]);
        *(uint4*)(outl + g + 8)  = make_uint4(lp[4],  lp[5],  lp[6],  lp[7]);
        *(uint4*)(outl + g + 16) = make_uint4(lp[8],  lp[9],  lp[10], lp[11]);
        *(uint4*)(outl + g + 24) = make_uint4(lp[12], lp[13], lp[14], lp[15]);
    }
}

// ---------------- wmma iteration kernel ----------------
// Per CTA: 32 rows, 8 warps. Constants: Bt[d][m] = 0.5*A[m][d] (split),
// Mo[m][c] = Mop (split). z fp32 in registers (lane = row, warp = 32-col block).
// Per iter: t = z@Bt (GEMM1, split t) ; s = t@Mo (GEMM2) ; y = 0.5z - s + rv;
// z += OMEGA*(max(2y-z,0) - y).
#define IT_BT_H 0
#define IT_BT_L 36864
#define IT_MO_H 73728
#define IT_MO_L 107520
#define IT_ZH   141312
#define IT_ZL   158208
#define IT_TH   175104
#define IT_TL   179712
#define IT_SC   184320
#define IT_SMEM 217600
#define ZB 264   // bf16 stride, 256-wide arrays (z, Mo)
#define TB 72    // bf16/f32 stride, 64-wide arrays (t, Bt)
#define SB 260   // f32 scratch stride (260 % 32 == 4 -> conflict-free lane-major LDS.128)

__device__ __forceinline__ void it_gemm1(const __nv_bfloat16* zh, const __nv_bfloat16* zl,
                                         const __nv_bfloat16* Bh, const __nv_bfloat16* Bl,
                                         float* scf, int tr, int tc) {
    wmma::fragment<wmma::accumulator, 16, 16, 16, float> acc;
    wmma::fill_fragment(acc, 0.f);
    #pragma unroll
    for (int k = 0; k < 16; k++) {
        wmma::fragment<wmma::matrix_a, 16, 16, 16, __nv_bfloat16, wmma::row_major> ah, al;
        wmma::fragment<wmma::matrix_b, 16, 16, 16, __nv_bfloat16, wmma::row_major> bh, bl;
        wmma::load_matrix_sync(ah, zh + tr * 16 * ZB + k * 16, ZB);
        wmma::load_matrix_sync(al, zl + tr * 16 * ZB + k * 16, ZB);
        wmma::load_matrix_sync(bh, Bh + k * 16 * TB + tc * 16, TB);
        wmma::load_matrix_sync(bl, Bl + k * 16 * TB + tc * 16, TB);
        wmma::mma_sync(acc, ah, bh, acc);
        wmma::mma_sync(acc, ah, bl, acc);
        wmma::mma_sync(acc, al, bh, acc);
    }
    wmma::store_matrix_sync(scf + tr * 16 * TB + tc * 16, acc, TB, wmma::mem_row_major);
}

__device__ __forceinline__ void it_gemm2(const __nv_bfloat16* th, const __nv_bfloat16* tl,
                                         const __nv_bfloat16* Mh, const __nv_bfloat16* Ml,
                                         float* scf, int tr, int tc) {
    wmma::fragment<wmma::accumulator, 16, 16, 16, float> acc[4];
    #pragma unroll
    for (int j = 0; j < 4; j++) wmma::fill_fragment(acc[j], 0.f);
    #pragma unroll
    for (int k = 0; k < 4; k++) {
        wmma::fragment<wmma::matrix_a, 16, 16, 16, __nv_bfloat16, wmma::row_major> ah, al;
        wmma::load_matrix_sync(ah, th + tr * 16 * TB + k * 16, TB);
        wmma::load_matrix_sync(al, tl + tr * 16 * TB + k * 16, TB);
        #pragma unroll
        for (int j = 0; j < 4; j++) {
            wmma::fragment<wmma::matrix_b, 16, 16, 16, __nv_bfloat16, wmma::row_major> bh, bl;
            wmma::load_matrix_sync(bh, Mh + k * 16 * ZB + tc * 64 + j * 16, ZB);
            wmma::load_matrix_sync(bl, Ml + k * 16 * ZB + tc * 64 + j * 16, ZB);
            wmma::mma_sync(acc[j], ah, bh, acc[j]);
            wmma::mma_sync(acc[j], ah, bl, acc[j]);
            wmma::mma_sync(acc[j], al, bh, acc[j]);
        }
    }
    #pragma unroll
    for (int j = 0; j < 4; j++)
        wmma::store_matrix_sync(scf + tr * 16 * SB + tc * 64 + j * 16, acc[j], SB, wmma::mem_row_major);
}

__global__ __launch_bounds__(256, 1) void iter_wmma(
    const float* __restrict__ y0g, const float* __restrict__ bcong,
    const float* __restrict__ Ag, float* __restrict__ outg,
    const int* __restrict__ nip) {
    extern __shared__ char smi[];
    __nv_bfloat16* Bt_h = (__nv_bfloat16*)(smi + IT_BT_H);
    __nv_bfloat16* Bt_l = (__nv_bfloat16*)(smi + IT_BT_L);
    __nv_bfloat16* Mo_h = (__nv_bfloat16*)(smi + IT_MO_H);
    __nv_bfloat16* Mo_l = (__nv_bfloat16*)(smi + IT_MO_L);
    __nv_bfloat16* zh   = (__nv_bfloat16*)(smi + IT_ZH);
    __nv_bfloat16* zl   = (__nv_bfloat16*)(smi + IT_ZL);
    __nv_bfloat16* th   = (__nv_bfloat16*)(smi + IT_TH);
    __nv_bfloat16* tl   = (__nv_bfloat16*)(smi + IT_TL);
    float*         scf  = (float*)(smi + IT_SC);

    const int tid = threadIdx.x, lane = tid & 31, w = tid >> 5;
    const int tr = w & 1, tc = w >> 1;
    const int row0 = blockIdx.x * 32;
    const int wc0 = w * 32;
    const int trow = tid >> 3, m0 = (tid & 7) * 8;
    const int ni = *nip;

    // stage Bt = 0.5*A^T split
    for (int i = tid; i < 64 * 256; i += 256) {
        int m = i >> 8, d = i & 255;
        float v = 0.5f * Ag[i];
        __nv_bfloat16 h = __float2bfloat16(v);
        Bt_h[d * TB + m] = h;
        Bt_l[d * TB + m] = __float2bfloat16(v - __bfloat162float(h));
    }
    // stage Mo = Mop split
    for (int i = tid; i < 64 * 256; i += 256) {
        int m = i >> 8, c = i & 255;
        float v = g_Mop[i];
        __nv_bfloat16 h = __float2bfloat16(v);
        Mo_h[m * ZB + c] = h;
        Mo_l[m * ZB + c] = __float2bfloat16(v - __bfloat162float(h));
    }
    // z state in registers; split into smem
    float z[32], rv[32];
    #pragma unroll
    for (int j = 0; j < 32; j += 2) {
        float2 v = *(const float2*)(y0g + (size_t)(row0 + lane) * 256 + wc0 + j);
        z[j] = v.x; z[j + 1] = v.y;
        __nv_bfloat16 h0 = __float2bfloat16(v.x), h1 = __float2bfloat16(v.y);
        __nv_bfloat16 l0 = __float2bfloat16(v.x - __bfloat162float(h0));
        __nv_bfloat16 l1 = __float2bfloat16(v.y - __bfloat162float(h1));
        *(uint32_t*)(zh + lane * ZB + wc0 + j) = pack_bf2(h0, h1);
        *(uint32_t*)(zl + lane * ZB + wc0 + j) = pack_bf2(l0, l1);
    }
    __syncthreads();

    // rv = 0.5*y0 - (0.5*y0@A^T - bcon) @ Mop
    it_gemm1(zh, zl, Bt_h, Bt_l, scf, tr, tc);
    __syncthreads();
    #pragma unroll
    for (int q = 0; q < 8; q += 2) {
        float v0 = scf[trow * TB + m0 + q]     - bcong[(size_t)(row0 + trow) * 64 + m0 + q];
        float v1 = scf[trow * TB + m0 + q + 1] - bcong[(size_t)(row0 + trow) * 64 + m0 + q + 1];
        __nv_bfloat16 h0 = __float2bfloat16(v0), h1 = __float2bfloat16(v1);
        __nv_bfloat16 l0 = __float2bfloat16(v0 - __bfloat162float(h0));
        __nv_bfloat16 l1 = __float2bfloat16(v1 - __bfloat162float(h1));
        *(uint32_t*)(th + trow * TB + m0 + q) = pack_bf2(h0, h1);
        *(uint32_t*)(tl + trow * TB + m0 + q) = pack_bf2(l0, l1);
    }
    __syncthreads();
    it_gemm2(th, tl, Mo_h, Mo_l, scf, tr, tc);
    __syncthreads();
    #pragma unroll
    for (int j = 0; j < 32; j += 2) {
        float2 sv = *(const float2*)(scf + lane * SB + wc0 + j);
        rv[j]     = 0.5f * z[j]     - sv.x;
        rv[j + 1] = 0.5f * z[j + 1] - sv.y;
    }

    for (int it = 0; it < ni; it++) {
        __syncthreads();   // protects scf + zh/zl across iterations
        it_gemm1(zh, zl, Bt_h, Bt_l, scf, tr, tc);
        __syncthreads();
        #pragma unroll
        for (int q = 0; q < 8; q += 2) {
            float v0 = scf[trow * TB + m0 + q];
            float v1 = scf[trow * TB + m0 + q + 1];
            __nv_bfloat16 h0 = __float2bfloat16(v0), h1 = __float2bfloat16(v1);
            __nv_bfloat16 l0 = __float2bfloat16(v0 - __bfloat162float(h0));
            __nv_bfloat16 l1 = __float2bfloat16(v1 - __bfloat162float(h1));
            *(uint32_t*)(th + trow * TB + m0 + q) = pack_bf2(h0, h1);
            *(uint32_t*)(tl + trow * TB + m0 + q) = pack_bf2(l0, l1);
        }
        __syncthreads();
        it_gemm2(th, tl, Mo_h, Mo_l, scf, tr, tc);
        __syncthreads();
        if (it == ni - 1) {
            #pragma unroll
            for (int j = 0; j < 32; j += 2) {
                float2 sv = *(const float2*)(scf + lane * SB + wc0 + j);
                float y0v = 0.5f * z[j]     - sv.x + rv[j];
                float y1v = 0.5f * z[j + 1] - sv.y + rv[j + 1];
                *(float2*)(outg + (size_t)(row0 + lane) * 256 + wc0 + j) = make_float2(y0v, y1v);
            }
        } else {
            #pragma unroll
            for (int j = 0; j < 32; j += 2) {
                float2 sv = *(const float2*)(scf + lane * SB + wc0 + j);
                float y0v = 0.5f * z[j]     - sv.x + rv[j];
                float y1v = 0.5f * z[j + 1] - sv.y + rv[j + 1];
                float w0 = fmaxf(2.f * y0v - z[j],     0.f);
                float w1 = fmaxf(2.f * y1v - z[j + 1], 0.f);
                z[j]     += OMEGA * (w0 - y0v);
                z[j + 1] += OMEGA * (w1 - y1v);
                __nv_bfloat16 h0 = __float2bfloat16(z[j]), h1 = __float2bfloat16(z[j + 1]);
                __nv_bfloat16 l0 = __float2bfloat16(z[j]     - __bfloat162float(h0));
                __nv_bfloat16 l1 = __float2bfloat16(z[j + 1] - __bfloat162float(h1));
                *(uint32_t*)(zh + lane * ZB + wc0 + j) = pack_bf2(h0, h1);
                *(uint32_t*)(zl + lane * ZB + wc0 + j) = pack_bf2(l0, l1);
            }
        }
    }
}

// =====================================================================
extern "C" void kernel_launch(void* const* d_in, const int* in_sizes, int n_in,
                              void* d_out, int out_size) {
    const float* x    = (const float*)d_in[0];
    const float* bcon = (const float*)d_in[1];
    const float* A    = (const float*)d_in[2];
    const float* W1   = (const float*)d_in[3];
    const float* b1   = (const float*)d_in[4];
    const float* W2   = (const float*)d_in[5];
    const float* b2   = (const float*)d_in[6];
    const float* W3   = (const float*)d_in[7];
    const float* b3   = (const float*)d_in[8];
    const float* Wout = (const float*)d_in[9];
    const float* bout = (const float*)d_in[10];
    const int*   nip  = (const int*)d_in[11];
    float* out = (float*)d_out;

    cudaFuncSetAttribute(setup_kernel, cudaFuncAttributeMaxDynamicSharedMemorySize, SETUP_SMEM);
    cudaFuncSetAttribute(iter_wmma,    cudaFuncAttributeMaxDynamicSharedMemorySize, IT_SMEM);

    void *py0;
    cudaGetSymbolAddress(&py0, g_y0);
    float* y0 = (float*)py0;
    void *pxh, *pxl, *p1h, *p1l, *p2h, *p2l;
    void *pw1h, *pw1l, *pw2h, *pw2l, *pw3h, *pw3l, *pw4h, *pw4l;
    cudaGetSymbolAddress(&pxh, g_xh);   cudaGetSymbolAddress(&pxl, g_xl);
    cudaGetSymbolAddress(&p1h, g_h1h);  cudaGetSymbolAddress(&p1l, g_h1l);
    cudaGetSymbolAddress(&p2h, g_h2h);  cudaGetSymbolAddress(&p2l, g_h2l);
    cudaGetSymbolAddress(&pw1h, g_w1h); cudaGetSymbolAddress(&pw1l, g_w1l);
    cudaGetSymbolAddress(&pw2h, g_w2h); cudaGetSymbolAddress(&pw2l, g_w2l);
    cudaGetSymbolAddress(&pw3h, g_w3h); cudaGetSymbolAddress(&pw3l, g_w3l);
    cudaGetSymbolAddress(&pw4h, g_w4h); cudaGetSymbolAddress(&pw4l, g_w4l);
    __nv_bfloat16 *xh = (__nv_bfloat16*)pxh, *xl = (__nv_bfloat16*)pxl;
    __nv_bfloat16 *h1h = (__nv_bfloat16*)p1h, *h1l = (__nv_bfloat16*)p1l;
    __nv_bfloat16 *h2h = (__nv_bfloat16*)p2h, *h2l = (__nv_bfloat16*)p2l;
    __nv_bfloat16 *w1h = (__nv_bfloat16*)pw1h, *w1l = (__nv_bfloat16*)pw1l;
    __nv_bfloat16 *w2h = (__nv_bfloat16*)pw2h, *w2l = (__nv_bfloat16*)pw2l;
    __nv_bfloat16 *w3h = (__nv_bfloat16*)pw3h, *w3l = (__nv_bfloat16*)pw3l;
    __nv_bfloat16 *w4h = (__nv_bfloat16*)pw4h, *w4l = (__nv_bfloat16*)pw4l;

    cvt_split<<<(4096 * 128 + 255) / 256, 256>>>(x, xh, xl, 4096 * 128);
    cvt_split<<<(128 * 512 + 255) / 256, 256>>>(W1, w1h, w1l, 128 * 512);
    cvt_split<<<(512 * 512 + 255) / 256, 256>>>(W2, w2h, w2l, 512 * 512);
    cvt_split<<<(512 * 512 + 255) / 256, 256>>>(W3, w3h, w3l, 512 * 512);
    cvt_split<<<(512 * 256 + 255) / 256, 256>>>(Wout, w4h, w4l, 512 * 256);
    setup_kernel<<<1, 256, SETUP_SMEM>>>(A);

    gemm_wmma<true, false><<<dim3(8, 32), 256>>>(xh, xl, w1h, w1l, b1, nullptr, h1h, h1l, 4096, 512, 128);
    gemm_wmma<true, false><<<dim3(8, 32), 256>>>(h1h, h1l, w2h, w2l, b2, nullptr, h2h, h2l, 4096, 512, 512);
    gemm_wmma<true, false><<<dim3(8, 32), 256>>>(h2h, h2l, w3h, w3l, b3, nullptr, h1h, h1l, 4096, 512, 512);
    gemm_wmma<false, true><<<dim3(4, 32), 256>>>(h1h, h1l, w4h, w4l, bout, y0, nullptr, nullptr, 4096, 256, 512);

    iter_wmma<<<128, 256, IT_SMEM>>>(y0, bcon, A, out, nip);
}

// round 14
// speedup vs baseline: 1.7057x; 1.0428x over previous
#include <cuda_runtime.h>
#include <cuda_bf16.h>
#include <cstdint>
#include <mma.h>

using namespace nvcuda;

#define OMEGA 1.7f
typedef unsigned long long ull;

// ---------------- global scratch (allocations are forbidden) ----------------
__device__ float g_Mop[64 * 256];
__device__ float g_y0[4096 * 256];
__device__ __nv_bfloat16 g_xh[4096 * 128],  g_xl[4096 * 128];
__device__ __nv_bfloat16 g_h1h[4096 * 512], g_h1l[4096 * 512];
__device__ __nv_bfloat16 g_h2h[4096 * 512], g_h2l[4096 * 512];
__device__ __nv_bfloat16 g_w1h[128 * 512],  g_w1l[128 * 512];
__device__ __nv_bfloat16 g_w2h[512 * 512],  g_w2l[512 * 512];
__device__ __nv_bfloat16 g_w3h[512 * 512],  g_w3l[512 * 512];
__device__ __nv_bfloat16 g_w4h[512 * 256],  g_w4l[512 * 256];

__device__ __forceinline__ uint32_t pack_bf2(__nv_bfloat16 a, __nv_bfloat16 b) {
    return (uint32_t)__bfloat16_as_ushort(a) | ((uint32_t)__bfloat16_as_ushort(b) << 16);
}

// ---------------- split converts ----------------
__global__ void cvt_split(const float* __restrict__ in, __nv_bfloat16* __restrict__ hi,
                          __nv_bfloat16* __restrict__ lo, int n) {
    int i = blockIdx.x * 256 + threadIdx.x;
    if (i < n) {
        float v = in[i];
        __nv_bfloat16 h = __float2bfloat16(v);
        hi[i] = h;
        lo[i] = __float2bfloat16(v - __bfloat162float(h));
    }
}

// ---------------- setup: Mop = inv(A A^T) @ A ----------------
#define SETUP_SMEM ((64 * 260 + 64 * 130) * 4)
__global__ void setup_kernel(const float* __restrict__ A) {
    extern __shared__ float sm[];
    float* As = sm;
    float* G  = sm + 64 * 260;
    __shared__ float colp[64];
    const int tid = threadIdx.x;
    for (int i = tid; i < 64 * 64; i += 256) {
        int m = i >> 6, d = (i & 63) << 2;
        *(float4*)(As + m * 260 + d) = *(const float4*)(A + m * 256 + d);
    }
    __syncthreads();
    for (int o = tid; o < 64 * 64; o += 256) {
        int i = o >> 6, j = o & 63;
        const float4* ai = (const float4*)(As + i * 260);
        const float4* aj = (const float4*)(As + j * 260);
        float s = 0.f;
        #pragma unroll 8
        for (int d4 = 0; d4 < 64; d4++) {
            float4 a = ai[d4], b = aj[d4];
            s += a.x * b.x + a.y * b.y + a.z * b.z + a.w * b.w;
        }
        G[i * 130 + j] = s;
        G[i * 130 + 64 + j] = (i == j) ? 1.f : 0.f;
    }
    __syncthreads();
    for (int p = 0; p < 64; p++) {
        float pinv = 1.f / G[p * 130 + p];
        if (tid < 64) colp[tid] = G[tid * 130 + p];
        __syncthreads();
        if (tid < 128) G[p * 130 + tid] *= pinv;
        __syncthreads();
        for (int e = tid; e < 64 * 128; e += 256) {
            int i = e >> 7, c = e & 127;
            if (i != p) G[i * 130 + c] -= colp[i] * G[p * 130 + c];
        }
        __syncthreads();
    }
    for (int o = tid; o < 64 * 256; o += 256) {
        int m = o >> 8, d = o & 255;
        float s = 0.f;
        #pragma unroll 8
        for (int j = 0; j < 64; j++) s += G[m * 130 + 64 + j] * As[j * 260 + d];
        g_Mop[o] = s;
    }
}

// ---------------- wmma trunk GEMM (split-bf16, 3 terms) -- unchanged ----------------
#define ALD 40
#define BLD 72
#define ELD 36

template <bool RELU, bool F32OUT>
__global__ __launch_bounds__(256) void gemm_wmma(
    const __nv_bfloat16* __restrict__ Ah, const __nv_bfloat16* __restrict__ Al,
    const __nv_bfloat16* __restrict__ Bh, const __nv_bfloat16* __restrict__ Bl,
    const float* __restrict__ bias, float* __restrict__ outf,
    __nv_bfloat16* __restrict__ outh, __nv_bfloat16* __restrict__ outl,
    int M, int N, int K) {
    __shared__ char smbuf[36864];
    __shared__ float sbias[64];
    __nv_bfloat16* As_h = (__nv_bfloat16*)smbuf;
    __nv_bfloat16* As_l = As_h + 128 * ALD;
    __nv_bfloat16* Bs_h = As_l + 128 * ALD;
    __nv_bfloat16* Bs_l = Bs_h + 32 * BLD;
    float* ep = (float*)smbuf;

    const int tid = threadIdx.x, lane = tid & 31, wid = tid >> 5;
    const int wr = wid & 3, wc = wid >> 2;
    const int bm = blockIdx.y * 128, bn = blockIdx.x * 64;

    if (tid < 64) sbias[tid] = bias[bn + tid];

    wmma::fragment<wmma::accumulator, 16, 16, 16, float> acc[2][2];
    #pragma unroll
    for (int i = 0; i < 2; i++)
        #pragma unroll
        for (int j = 0; j < 2; j++) wmma::fill_fragment(acc[i][j], 0.f);

    const int arow = tid >> 2, aseg = (tid & 3) * 8;
    const int brow = tid >> 3, bseg = (tid & 7) * 8;

    for (int k0 = 0; k0 < K; k0 += 32) {
        __syncthreads();
        #pragma unroll
        for (int rr = 0; rr < 2; rr++) {
            int row = arow + rr * 64;
            size_t g = (size_t)(bm + row) * K + k0 + aseg;
            *(uint4*)(As_h + row * ALD + aseg) = *(const uint4*)(Ah + g);
            *(uint4*)(As_l + row * ALD + aseg) = *(const uint4*)(Al + g);
        }
        {
            size_t g = (size_t)(k0 + brow) * N + bn + bseg;
            *(uint4*)(Bs_h + brow * BLD + bseg) = *(const uint4*)(Bh + g);
            *(uint4*)(Bs_l + brow * BLD + bseg) = *(const uint4*)(Bl + g);
        }
        __syncthreads();

        #pragma unroll
        for (int kk = 0; kk < 32; kk += 16) {
            wmma::fragment<wmma::matrix_a, 16, 16, 16, __nv_bfloat16, wmma::row_major> ah[2], al[2];
            wmma::fragment<wmma::matrix_b, 16, 16, 16, __nv_bfloat16, wmma::row_major> bh[2], bl[2];
            #pragma unroll
            for (int i = 0; i < 2; i++) {
                wmma::load_matrix_sync(ah[i], As_h + (wr * 32 + i * 16) * ALD + kk, ALD);
                wmma::load_matrix_sync(al[i], As_l + (wr * 32 + i * 16) * ALD + kk, ALD);
            }
            #pragma unroll
            for (int j = 0; j < 2; j++) {
                wmma::load_matrix_sync(bh[j], Bs_h + kk * BLD + wc * 32 + j * 16, BLD);
                wmma::load_matrix_sync(bl[j], Bs_l + kk * BLD + wc * 32 + j * 16, BLD);
            }
            #pragma unroll
            for (int i = 0; i < 2; i++)
                #pragma unroll
                for (int j = 0; j < 2; j++) {
                    wmma::mma_sync(acc[i][j], ah[i], bh[j], acc[i][j]);
                    wmma::mma_sync(acc[i][j], ah[i], bl[j], acc[i][j]);
                    wmma::mma_sync(acc[i][j], al[i], bh[j], acc[i][j]);
                }
        }
    }
    __syncthreads();

    float* wep = ep + wid * 32 * ELD;
    #pragma unroll
    for (int i = 0; i < 2; i++)
        #pragma unroll
        for (int j = 0; j < 2; j++)
            wmma::store_matrix_sync(wep + i * 16 * ELD + j * 16, acc[i][j], ELD, wmma::mem_row_major);
    __syncwarp();

    const int grow = bm + wr * 32 + lane;
    const int gcol0 = bn + wc * 32;
    if (F32OUT) {
        float* op = outf + (size_t)grow * N + gcol0;
        #pragma unroll
        for (int c = 0; c < 32; c += 4) {
            float4 v = *(float4*)(wep + lane * ELD + c);
            v.x += sbias[wc * 32 + c + 0];
            v.y += sbias[wc * 32 + c + 1];
            v.z += sbias[wc * 32 + c + 2];
            v.w += sbias[wc * 32 + c + 3];
            if (RELU) {
                v.x = fmaxf(v.x, 0.f); v.y = fmaxf(v.y, 0.f);
                v.z = fmaxf(v.z, 0.f); v.w = fmaxf(v.w, 0.f);
            }
            *(float4*)(op + c) = v;
        }
    } else {
        uint32_t hp[16], lp[16];
        #pragma unroll
        for (int c = 0; c < 32; c += 2) {
            float v0 = wep[lane * ELD + c]     + sbias[wc * 32 + c];
            float v1 = wep[lane * ELD + c + 1] + sbias[wc * 32 + c + 1];
            if (RELU) { v0 = fmaxf(v0, 0.f); v1 = fmaxf(v1, 0.f); }
            __nv_bfloat16 h0 = __float2bfloat16(v0), h1 = __float2bfloat16(v1);
            __nv_bfloat16 l0 = __float2bfloat16(v0 - __bfloat162float(h0));
            __nv_bfloat16 l1 = __float2bfloat16(v1 - __bfloat162float(h1));
            hp[c >> 1] = pack_bf2(h0, h1);
            lp[c >> 1] = pack_bf2(l0, l1);
        }
        size_t g = (size_t)grow * N + gcol0;
        *(uint4*)(outh + g)      = make_uint4(hp[0],  hp[1],  hp[2],  hp[3]);
        *(uint4*)(outh + g + 8)  = make_uint4(hp[4],  hp[5],  hp[6],  hp[7]);
        *(uint4*)(outh + g + 16) = make_uint4(hp[8],  hp[9],  hp[10], hp[11]);
        *(uint4*)(outh + g + 24) = make_uint4(hp[12], hp[13], hp[14], hp[15]);
        *(uint4*)(outl + g)      = make_uint4(lp[0],  lp[1],  lp[2],  lp[3]);
        *(uint4*)(outl + g + 8)  = make_uint4(lp[4],  lp[5],  lp[6],  lp[7]);
        *(uint4*)(outl + g + 16) = make_uint4(lp[8],  lp[9],  lp[10], lp[11]);
        *(uint4*)(outl + g + 24) = make_uint4(lp[12], lp[13], lp[14], lp[15]);
    }
}

// ---------------- wmma iteration kernel: 512 threads (16 warps) ----------------
// gemm1 K-split across warp pairs into sc1a/sc1b; split phase adds partials.
// gemm2: 2 tiles/warp. Epilogue: 16 cols/thread, z fp32 in registers.
#define IT_BT_H 0
#define IT_BT_L 36864
#define IT_MO_H 73728
#define IT_MO_L 107520
#define IT_ZH   141312
#define IT_ZL   158208
#define IT_TH   175104
#define IT_TL   179712
#define IT_SC   184320
#define IT_SMEM 217600
#define ZB 264   // bf16 stride, 256-wide arrays (z, Mo)
#define TB 72    // bf16/f32 stride, 64-wide arrays (t, Bt, sc1)
#define SB 260   // f32 scratch stride
#define SC1B_OFF 2304   // floats: 32*72

__device__ __forceinline__ void it_gemm1(const __nv_bfloat16* zh, const __nv_bfloat16* zl,
                                         const __nv_bfloat16* Bh, const __nv_bfloat16* Bl,
                                         float* sc1, int tr, int tc, int kh) {
    wmma::fragment<wmma::accumulator, 16, 16, 16, float> acc;
    wmma::fill_fragment(acc, 0.f);
    #pragma unroll
    for (int k = 0; k < 8; k++) {
        int kk = kh * 8 + k;
        wmma::fragment<wmma::matrix_a, 16, 16, 16, __nv_bfloat16, wmma::row_major> ah, al;
        wmma::fragment<wmma::matrix_b, 16, 16, 16, __nv_bfloat16, wmma::row_major> bh, bl;
        wmma::load_matrix_sync(ah, zh + tr * 16 * ZB + kk * 16, ZB);
        wmma::load_matrix_sync(al, zl + tr * 16 * ZB + kk * 16, ZB);
        wmma::load_matrix_sync(bh, Bh + kk * 16 * TB + tc * 16, TB);
        wmma::load_matrix_sync(bl, Bl + kk * 16 * TB + tc * 16, TB);
        wmma::mma_sync(acc, ah, bh, acc);
        wmma::mma_sync(acc, ah, bl, acc);
        wmma::mma_sync(acc, al, bh, acc);
    }
    wmma::store_matrix_sync(sc1 + tr * 16 * TB + tc * 16, acc, TB, wmma::mem_row_major);
}

__device__ __forceinline__ void it_gemm2(const __nv_bfloat16* th, const __nv_bfloat16* tl,
                                         const __nv_bfloat16* Mh, const __nv_bfloat16* Ml,
                                         float* scf, int tr, int tcol) {
    wmma::fragment<wmma::accumulator, 16, 16, 16, float> acc[2];
    #pragma unroll
    for (int j = 0; j < 2; j++) wmma::fill_fragment(acc[j], 0.f);
    #pragma unroll
    for (int k = 0; k < 4; k++) {
        wmma::fragment<wmma::matrix_a, 16, 16, 16, __nv_bfloat16, wmma::row_major> ah, al;
        wmma::load_matrix_sync(ah, th + tr * 16 * TB + k * 16, TB);
        wmma::load_matrix_sync(al, tl + tr * 16 * TB + k * 16, TB);
        #pragma unroll
        for (int j = 0; j < 2; j++) {
            wmma::fragment<wmma::matrix_b, 16, 16, 16, __nv_bfloat16, wmma::row_major> bh, bl;
            wmma::load_matrix_sync(bh, Mh + k * 16 * ZB + tcol * 32 + j * 16, ZB);
            wmma::load_matrix_sync(bl, Ml + k * 16 * ZB + tcol * 32 + j * 16, ZB);
            wmma::mma_sync(acc[j], ah, bh, acc[j]);
            wmma::mma_sync(acc[j], ah, bl, acc[j]);
            wmma::mma_sync(acc[j], al, bh, acc[j]);
        }
    }
    #pragma unroll
    for (int j = 0; j < 2; j++)
        wmma::store_matrix_sync(scf + tr * 16 * SB + tcol * 32 + j * 16, acc[j], SB, wmma::mem_row_major);
}

__global__ __launch_bounds__(512, 1) void iter_wmma(
    const float* __restrict__ y0g, const float* __restrict__ bcong,
    const float* __restrict__ Ag, float* __restrict__ outg,
    const int* __restrict__ nip) {
    extern __shared__ char smi[];
    __nv_bfloat16* Bt_h = (__nv_bfloat16*)(smi + IT_BT_H);
    __nv_bfloat16* Bt_l = (__nv_bfloat16*)(smi + IT_BT_L);
    __nv_bfloat16* Mo_h = (__nv_bfloat16*)(smi + IT_MO_H);
    __nv_bfloat16* Mo_l = (__nv_bfloat16*)(smi + IT_MO_L);
    __nv_bfloat16* zh   = (__nv_bfloat16*)(smi + IT_ZH);
    __nv_bfloat16* zl   = (__nv_bfloat16*)(smi + IT_ZL);
    __nv_bfloat16* th   = (__nv_bfloat16*)(smi + IT_TH);
    __nv_bfloat16* tl   = (__nv_bfloat16*)(smi + IT_TL);
    float*         scf  = (float*)(smi + IT_SC);
    float*         sc1a = scf;                 // overlay: dead across barriers
    float*         sc1b = scf + SC1B_OFF;

    const int tid = threadIdx.x, lane = tid & 31, w = tid >> 5;   // 16 warps
    const int g1_tr = w & 1, g1_tc = (w >> 1) & 3, g1_kh = w >> 3;
    const int g2_tr = w & 1, g2_tc = w >> 1;                       // 0..7
    const int row0 = blockIdx.x * 32;
    const int wc0 = w * 16;                                        // epilogue cols
    const int s_row = tid >> 4, s_m0 = (tid & 15) * 4;             // split phase
    const int ni = *nip;

    // stage Bt = 0.5*A^T split
    for (int i = tid; i < 64 * 256; i += 512) {
        int m = i >> 8, d = i & 255;
        float v = 0.5f * Ag[i];
        __nv_bfloat16 h = __float2bfloat16(v);
        Bt_h[d * TB + m] = h;
        Bt_l[d * TB + m] = __float2bfloat16(v - __bfloat162float(h));
    }
    // stage Mo = Mop split
    for (int i = tid; i < 64 * 256; i += 512) {
        int m = i >> 8, c = i & 255;
        float v = g_Mop[i];
        __nv_bfloat16 h = __float2bfloat16(v);
        Mo_h[m * ZB + c] = h;
        Mo_l[m * ZB + c] = __float2bfloat16(v - __bfloat162float(h));
    }
    // z state in registers (16 cols/thread); split into smem
    float z[16], rv[16];
    #pragma unroll
    for (int j = 0; j < 16; j += 2) {
        float2 v = *(const float2*)(y0g + (size_t)(row0 + lane) * 256 + wc0 + j);
        z[j] = v.x; z[j + 1] = v.y;
        __nv_bfloat16 h0 = __float2bfloat16(v.x), h1 = __float2bfloat16(v.y);
        __nv_bfloat16 l0 = __float2bfloat16(v.x - __bfloat162float(h0));
        __nv_bfloat16 l1 = __float2bfloat16(v.y - __bfloat162float(h1));
        *(uint32_t*)(zh + lane * ZB + wc0 + j) = pack_bf2(h0, h1);
        *(uint32_t*)(zl + lane * ZB + wc0 + j) = pack_bf2(l0, l1);
    }
    __syncthreads();

    // ---- rv init: t = 0.5*y0@A^T - bcon ; rv = 0.5*y0 - t@Mop ----
    it_gemm1(zh, zl, Bt_h, Bt_l, g1_kh ? sc1b : sc1a, g1_tr, g1_tc, g1_kh);
    __syncthreads();
    {
        float4 va = *(const float4*)(sc1a + s_row * TB + s_m0);
        float4 vb = *(const float4*)(sc1b + s_row * TB + s_m0);
        const float* bp = bcong + (size_t)(row0 + s_row) * 64 + s_m0;
        float f[4] = {va.x + vb.x - bp[0], va.y + vb.y - bp[1],
                      va.z + vb.z - bp[2], va.w + vb.w - bp[3]};
        #pragma unroll
        for (int q = 0; q < 4; q += 2) {
            __nv_bfloat16 h0 = __float2bfloat16(f[q]), h1 = __float2bfloat16(f[q + 1]);
            __nv_bfloat16 l0 = __float2bfloat16(f[q]     - __bfloat162float(h0));
            __nv_bfloat16 l1 = __float2bfloat16(f[q + 1] - __bfloat162float(h1));
            *(uint32_t*)(th + s_row * TB + s_m0 + q) = pack_bf2(h0, h1);
            *(uint32_t*)(tl + s_row * TB + s_m0 + q) = pack_bf2(l0, l1);
        }
    }
    __syncthreads();
    it_gemm2(th, tl, Mo_h, Mo_l, scf, g2_tr, g2_tc);
    __syncthreads();
    #pragma unroll
    for (int j = 0; j < 16; j += 2) {
        float2 sv = *(const float2*)(scf + lane * SB + wc0 + j);
        rv[j]     = 0.5f * z[j]     - sv.x;
        rv[j + 1] = 0.5f * z[j + 1] - sv.y;
    }

    // ---- main loop ----
    for (int it = 0; it < ni; it++) {
        __syncthreads();   // scf reads done; zh/zl stable
        it_gemm1(zh, zl, Bt_h, Bt_l, g1_kh ? sc1b : sc1a, g1_tr, g1_tc, g1_kh);
        __syncthreads();
        {
            float4 va = *(const float4*)(sc1a + s_row * TB + s_m0);
            float4 vb = *(const float4*)(sc1b + s_row * TB + s_m0);
            float f[4] = {va.x + vb.x, va.y + vb.y, va.z + vb.z, va.w + vb.w};
            #pragma unroll
            for (int q = 0; q < 4; q += 2) {
                __nv_bfloat16 h0 = __float2bfloat16(f[q]), h1 = __float2bfloat16(f[q + 1]);
                __nv_bfloat16 l0 = __float2bfloat16(f[q]     - __bfloat162float(h0));
                __nv_bfloat16 l1 = __float2bfloat16(f[q + 1] - __bfloat162float(h1));
                *(uint32_t*)(th + s_row * TB + s_m0 + q) = pack_bf2(h0, h1);
                *(uint32_t*)(tl + s_row * TB + s_m0 + q) = pack_bf2(l0, l1);
            }
        }
        __syncthreads();
        it_gemm2(th, tl, Mo_h, Mo_l, scf, g2_tr, g2_tc);
        __syncthreads();
        if (it == ni - 1) {
            #pragma unroll
            for (int j = 0; j < 16; j += 2) {
                float2 sv = *(const float2*)(scf + lane * SB + wc0 + j);
                float y0v = 0.5f * z[j]     - sv.x + rv[j];
                float y1v = 0.5f * z[j + 1] - sv.y + rv[j + 1];
                *(float2*)(outg + (size_t)(row0 + lane) * 256 + wc0 + j) = make_float2(y0v, y1v);
            }
        } else {
            #pragma unroll
            for (int j = 0; j < 16; j += 2) {
                float2 sv = *(const float2*)(scf + lane * SB + wc0 + j);
                float y0v = 0.5f * z[j]     - sv.x + rv[j];
                float y1v = 0.5f * z[j + 1] - sv.y + rv[j + 1];
                float w0 = fmaxf(2.f * y0v - z[j],     0.f);
                float w1 = fmaxf(2.f * y1v - z[j + 1], 0.f);
                z[j]     += OMEGA * (w0 - y0v);
                z[j + 1] += OMEGA * (w1 - y1v);
                __nv_bfloat16 h0 = __float2bfloat16(z[j]), h1 = __float2bfloat16(z[j + 1]);
                __nv_bfloat16 l0 = __float2bfloat16(z[j]     - __bfloat162float(h0));
                __nv_bfloat16 l1 = __float2bfloat16(z[j + 1] - __bfloat162float(h1));
                *(uint32_t*)(zh + lane * ZB + wc0 + j) = pack_bf2(h0, h1);
                *(uint32_t*)(zl + lane * ZB + wc0 + j) = pack_bf2(l0, l1);
            }
        }
    }
}

// =====================================================================
extern "C" void kernel_launch(void* const* d_in, const int* in_sizes, int n_in,
                              void* d_out, int out_size) {
    const float* x    = (const float*)d_in[0];
    const float* bcon = (const float*)d_in[1];
    const float* A    = (const float*)d_in[2];
    const float* W1   = (const float*)d_in[3];
    const float* b1   = (const float*)d_in[4];
    const float* W2   = (const float*)d_in[5];
    const float* b2   = (const float*)d_in[6];
    const float* W3   = (const float*)d_in[7];
    const float* b3   = (const float*)d_in[8];
    const float* Wout = (const float*)d_in[9];
    const float* bout = (const float*)d_in[10];
    const int*   nip  = (const int*)d_in[11];
    float* out = (float*)d_out;

    cudaFuncSetAttribute(setup_kernel, cudaFuncAttributeMaxDynamicSharedMemorySize, SETUP_SMEM);
    cudaFuncSetAttribute(iter_wmma,    cudaFuncAttributeMaxDynamicSharedMemorySize, IT_SMEM);

    void *py0;
    cudaGetSymbolAddress(&py0, g_y0);
    float* y0 = (float*)py0;
    void *pxh, *pxl, *p1h, *p1l, *p2h, *p2l;
    void *pw1h, *pw1l, *pw2h, *pw2l, *pw3h, *pw3l, *pw4h, *pw4l;
    cudaGetSymbolAddress(&pxh, g_xh);   cudaGetSymbolAddress(&pxl, g_xl);
    cudaGetSymbolAddress(&p1h, g_h1h);  cudaGetSymbolAddress(&p1l, g_h1l);
    cudaGetSymbolAddress(&p2h, g_h2h);  cudaGetSymbolAddress(&p2l, g_h2l);
    cudaGetSymbolAddress(&pw1h, g_w1h); cudaGetSymbolAddress(&pw1l, g_w1l);
    cudaGetSymbolAddress(&pw2h, g_w2h); cudaGetSymbolAddress(&pw2l, g_w2l);
    cudaGetSymbolAddress(&pw3h, g_w3h); cudaGetSymbolAddress(&pw3l, g_w3l);
    cudaGetSymbolAddress(&pw4h, g_w4h); cudaGetSymbolAddress(&pw4l, g_w4l);
    __nv_bfloat16 *xh = (__nv_bfloat16*)pxh, *xl = (__nv_bfloat16*)pxl;
    __nv_bfloat16 *h1h = (__nv_bfloat16*)p1h, *h1l = (__nv_bfloat16*)p1l;
    __nv_bfloat16 *h2h = (__nv_bfloat16*)p2h, *h2l = (__nv_bfloat16*)p2l;
    __nv_bfloat16 *w1h = (__nv_bfloat16*)pw1h, *w1l = (__nv_bfloat16*)pw1l;
    __nv_bfloat16 *w2h = (__nv_bfloat16*)pw2h, *w2l = (__nv_bfloat16*)pw2l;
    __nv_bfloat16 *w3h = (__nv_bfloat16*)pw3h, *w3l = (__nv_bfloat16*)pw3l;
    __nv_bfloat16 *w4h = (__nv_bfloat16*)pw4h, *w4l = (__nv_bfloat16*)pw4l;

    cvt_split<<<(4096 * 128 + 255) / 256, 256>>>(x, xh, xl, 4096 * 128);
    cvt_split<<<(128 * 512 + 255) / 256, 256>>>(W1, w1h, w1l, 128 * 512);
    cvt_split<<<(512 * 512 + 255) / 256, 256>>>(W2, w2h, w2l, 512 * 512);
    cvt_split<<<(512 * 512 + 255) / 256, 256>>>(W3, w3h, w3l, 512 * 512);
    cvt_split<<<(512 * 256 + 255) / 256, 256>>>(Wout, w4h, w4l, 512 * 256);
    setup_kernel<<<1, 256, SETUP_SMEM>>>(A);

    gemm_wmma<true, false><<<dim3(8, 32), 256>>>(xh, xl, w1h, w1l, b1, nullptr, h1h, h1l, 4096, 512, 128);
    gemm_wmma<true, false><<<dim3(8, 32), 256>>>(h1h, h1l, w2h, w2l, b2, nullptr, h2h, h2l, 4096, 512, 512);
    gemm_wmma<true, false><<<dim3(8, 32), 256>>>(h2h, h2l, w3h, w3l, b3, nullptr, h1h, h1l, 4096, 512, 512);
    gemm_wmma<false, true><<<dim3(4, 32), 256>>>(h1h, h1l, w4h, w4l, bout, y0, nullptr, nullptr, 4096, 256, 512);

    iter_wmma<<<128, 512, IT_SMEM>>>(y0, bcon, A, out, nip);
}

// round 15
// speedup vs baseline: 1.7281x; 1.0131x over previous
#include <cuda_runtime.h>
#include <cuda_bf16.h>
#include <cstdint>
#include <mma.h>

using namespace nvcuda;

#define OMEGA 1.7f
typedef unsigned long long ull;

// ---------------- global scratch (allocations are forbidden) ----------------
__device__ float g_Mop[64 * 256];
__device__ float g_y0[4096 * 256];
__device__ __nv_bfloat16 g_xh[4096 * 128],  g_xl[4096 * 128];
__device__ __nv_bfloat16 g_h1h[4096 * 512], g_h1l[4096 * 512];
__device__ __nv_bfloat16 g_h2h[4096 * 512], g_h2l[4096 * 512];
__device__ __nv_bfloat16 g_w1h[128 * 512],  g_w1l[128 * 512];
__device__ __nv_bfloat16 g_w2h[512 * 512],  g_w2l[512 * 512];
__device__ __nv_bfloat16 g_w3h[512 * 512],  g_w3l[512 * 512];
__device__ __nv_bfloat16 g_w4h[512 * 256],  g_w4l[512 * 256];

__device__ __forceinline__ uint32_t pack_bf2(__nv_bfloat16 a, __nv_bfloat16 b) {
    return (uint32_t)__bfloat16_as_ushort(a) | ((uint32_t)__bfloat16_as_ushort(b) << 16);
}

// ---------------- split converts ----------------
__global__ void cvt_split(const float* __restrict__ in, __nv_bfloat16* __restrict__ hi,
                          __nv_bfloat16* __restrict__ lo, int n) {
    int i = blockIdx.x * 256 + threadIdx.x;
    if (i < n) {
        float v = in[i];
        __nv_bfloat16 h = __float2bfloat16(v);
        hi[i] = h;
        lo[i] = __float2bfloat16(v - __bfloat162float(h));
    }
}

// ---------------- setup: Mop = inv(A A^T) @ A ----------------
#define SETUP_SMEM ((64 * 260 + 64 * 130) * 4)
__global__ void setup_kernel(const float* __restrict__ A) {
    extern __shared__ float sm[];
    float* As = sm;
    float* G  = sm + 64 * 260;
    __shared__ float colp[64];
    const int tid = threadIdx.x;
    for (int i = tid; i < 64 * 64; i += 256) {
        int m = i >> 6, d = (i & 63) << 2;
        *(float4*)(As + m * 260 + d) = *(const float4*)(A + m * 256 + d);
    }
    __syncthreads();
    for (int o = tid; o < 64 * 64; o += 256) {
        int i = o >> 6, j = o & 63;
        const float4* ai = (const float4*)(As + i * 260);
        const float4* aj = (const float4*)(As + j * 260);
        float s = 0.f;
        #pragma unroll 8
        for (int d4 = 0; d4 < 64; d4++) {
            float4 a = ai[d4], b = aj[d4];
            s += a.x * b.x + a.y * b.y + a.z * b.z + a.w * b.w;
        }
        G[i * 130 + j] = s;
        G[i * 130 + 64 + j] = (i == j) ? 1.f : 0.f;
    }
    __syncthreads();
    for (int p = 0; p < 64; p++) {
        float pinv = 1.f / G[p * 130 + p];
        if (tid < 64) colp[tid] = G[tid * 130 + p];
        __syncthreads();
        if (tid < 128) G[p * 130 + tid] *= pinv;
        __syncthreads();
        for (int e = tid; e < 64 * 128; e += 256) {
            int i = e >> 7, c = e & 127;
            if (i != p) G[i * 130 + c] -= colp[i] * G[p * 130 + c];
        }
        __syncthreads();
    }
    for (int o = tid; o < 64 * 256; o += 256) {
        int m = o >> 8, d = o & 255;
        float s = 0.f;
        #pragma unroll 8
        for (int j = 0; j < 64; j++) s += G[m * 130 + 64 + j] * As[j * 260 + d];
        g_Mop[o] = s;
    }
}

// ---------------- wmma trunk GEMM v2: 512 thr, BN=128, double-buffered ----------------
// C[128 x 128] = act(A @ B + bias); A [M][K] hi/lo bf16, B [K][N] hi/lo bf16.
// 16 warps (4x4), each 32x32 tile (2x2 frags), 3-term split accumulate.
#define ALD 40     // A smem row stride (bf16), 32 k + pad
#define BLD2 136   // B smem row stride (bf16), 128 n + pad
#define ELD 36     // epilogue f32 row stride
#define GA_BUF (128 * ALD)          // bf16 per A buffer
#define GB_BUF (32 * BLD2)          // bf16 per B buffer
#define GO_AH 0
#define GO_AL (2 * GA_BUF * 2)      // bytes: after As_h[2]
#define GO_BH (4 * GA_BUF * 2)
#define GO_BL (4 * GA_BUF * 2 + 2 * GB_BUF * 2)
#define GSMEM (4 * GA_BUF * 2 + 4 * GB_BUF * 2)   // 40960 + 34816 = 75776

template <bool RELU, bool F32OUT>
__global__ __launch_bounds__(512, 1) void gemm_wmma2(
    const __nv_bfloat16* __restrict__ Ah, const __nv_bfloat16* __restrict__ Al,
    const __nv_bfloat16* __restrict__ Bh, const __nv_bfloat16* __restrict__ Bl,
    const float* __restrict__ bias, float* __restrict__ outf,
    __nv_bfloat16* __restrict__ outh, __nv_bfloat16* __restrict__ outl,
    int M, int N, int K) {
    extern __shared__ char smg[];
    __shared__ float sbias[128];
    __nv_bfloat16* As_h = (__nv_bfloat16*)(smg + GO_AH);   // [2][128][ALD]
    __nv_bfloat16* As_l = (__nv_bfloat16*)(smg + GO_AL);
    __nv_bfloat16* Bs_h = (__nv_bfloat16*)(smg + GO_BH);   // [2][32][BLD2]
    __nv_bfloat16* Bs_l = (__nv_bfloat16*)(smg + GO_BL);
    float* ep = (float*)smg;                                // epilogue overlay

    const int tid = threadIdx.x, lane = tid & 31, wid = tid >> 5;
    const int wr = wid & 3, wc = wid >> 2;
    const int bm = blockIdx.y * 128, bn = blockIdx.x * 128;

    if (tid < 128) sbias[tid] = bias[bn + tid];

    wmma::fragment<wmma::accumulator, 16, 16, 16, float> acc[2][2];
    #pragma unroll
    for (int i = 0; i < 2; i++)
        #pragma unroll
        for (int j = 0; j < 2; j++) wmma::fill_fragment(acc[i][j], 0.f);

    const int arow = tid >> 2, aseg = (tid & 3) * 8;    // A: 128 x 32, 1 uint4/thr
    const int brow = tid >> 4, bseg = (tid & 15) * 8;   // B: 32 x 128, 1 uint4/thr

    const __nv_bfloat16* agh = Ah + (size_t)(bm + arow) * K + aseg;
    const __nv_bfloat16* agl = Al + (size_t)(bm + arow) * K + aseg;
    const __nv_bfloat16* bgh = Bh + (size_t)brow * N + bn + bseg;
    const __nv_bfloat16* bgl = Bl + (size_t)brow * N + bn + bseg;

    // preload block 0
    uint4 pah = *(const uint4*)(agh);
    uint4 pal = *(const uint4*)(agl);
    uint4 pbh = *(const uint4*)(bgh);
    uint4 pbl = *(const uint4*)(bgl);
    *(uint4*)(As_h + arow * ALD + aseg) = pah;
    *(uint4*)(As_l + arow * ALD + aseg) = pal;
    *(uint4*)(Bs_h + brow * BLD2 + bseg) = pbh;
    *(uint4*)(Bs_l + brow * BLD2 + bseg) = pbl;
    __syncthreads();

    const int nblk = K / 32;
    for (int blk = 0; blk < nblk; blk++) {
        int buf = blk & 1;
        if (blk + 1 < nblk) {
            pah = *(const uint4*)(agh + (blk + 1) * 32);
            pal = *(const uint4*)(agl + (blk + 1) * 32);
            pbh = *(const uint4*)(bgh + (size_t)(blk + 1) * 32 * N);
            pbl = *(const uint4*)(bgl + (size_t)(blk + 1) * 32 * N);
        }
        const __nv_bfloat16* ah_base = As_h + buf * GA_BUF;
        const __nv_bfloat16* al_base = As_l + buf * GA_BUF;
        const __nv_bfloat16* bh_base = Bs_h + buf * GB_BUF;
        const __nv_bfloat16* bl_base = Bs_l + buf * GB_BUF;

        #pragma unroll
        for (int kk = 0; kk < 32; kk += 16) {
            wmma::fragment<wmma::matrix_a, 16, 16, 16, __nv_bfloat16, wmma::row_major> afh[2], afl[2];
            wmma::fragment<wmma::matrix_b, 16, 16, 16, __nv_bfloat16, wmma::row_major> bfh[2], bfl[2];
            #pragma unroll
            for (int i = 0; i < 2; i++) {
                wmma::load_matrix_sync(afh[i], ah_base + (wr * 32 + i * 16) * ALD + kk, ALD);
                wmma::load_matrix_sync(afl[i], al_base + (wr * 32 + i * 16) * ALD + kk, ALD);
            }
            #pragma unroll
            for (int j = 0; j < 2; j++) {
                wmma::load_matrix_sync(bfh[j], bh_base + kk * BLD2 + wc * 32 + j * 16, BLD2);
                wmma::load_matrix_sync(bfl[j], bl_base + kk * BLD2 + wc * 32 + j * 16, BLD2);
            }
            #pragma unroll
            for (int i = 0; i < 2; i++)
                #pragma unroll
                for (int j = 0; j < 2; j++) {
                    wmma::mma_sync(acc[i][j], afh[i], bfh[j], acc[i][j]);
                    wmma::mma_sync(acc[i][j], afh[i], bfl[j], acc[i][j]);
                    wmma::mma_sync(acc[i][j], afl[i], bfh[j], acc[i][j]);
                }
        }

        if (blk + 1 < nblk) {
            int nb = buf ^ 1;
            *(uint4*)(As_h + nb * GA_BUF + arow * ALD + aseg) = pah;
            *(uint4*)(As_l + nb * GA_BUF + arow * ALD + aseg) = pal;
            *(uint4*)(Bs_h + nb * GB_BUF + brow * BLD2 + bseg) = pbh;
            *(uint4*)(Bs_l + nb * GB_BUF + brow * BLD2 + bseg) = pbl;
        }
        __syncthreads();
    }

    // epilogue: per-warp f32 staging region (overlay; all buffers dead)
    float* wep = ep + wid * 32 * ELD;
    #pragma unroll
    for (int i = 0; i < 2; i++)
        #pragma unroll
        for (int j = 0; j < 2; j++)
            wmma::store_matrix_sync(wep + i * 16 * ELD + j * 16, acc[i][j], ELD, wmma::mem_row_major);
    __syncwarp();

    const int grow = bm + wr * 32 + lane;
    const int gcol0 = bn + wc * 32;
    if (F32OUT) {
        float* op = outf + (size_t)grow * N + gcol0;
        #pragma unroll
        for (int c = 0; c < 32; c += 4) {
            float4 v = *(float4*)(wep + lane * ELD + c);
            v.x += sbias[wc * 32 + c + 0];
            v.y += sbias[wc * 32 + c + 1];
            v.z += sbias[wc * 32 + c + 2];
            v.w += sbias[wc * 32 + c + 3];
            if (RELU) {
                v.x = fmaxf(v.x, 0.f); v.y = fmaxf(v.y, 0.f);
                v.z = fmaxf(v.z, 0.f); v.w = fmaxf(v.w, 0.f);
            }
            *(float4*)(op + c) = v;
        }
    } else {
        uint32_t hp[16], lp[16];
        #pragma unroll
        for (int c = 0; c < 32; c += 2) {
            float v0 = wep[lane * ELD + c]     + sbias[wc * 32 + c];
            float v1 = wep[lane * ELD + c + 1] + sbias[wc * 32 + c + 1];
            if (RELU) { v0 = fmaxf(v0, 0.f); v1 = fmaxf(v1, 0.f); }
            __nv_bfloat16 h0 = __float2bfloat16(v0), h1 = __float2bfloat16(v1);
            __nv_bfloat16 l0 = __float2bfloat16(v0 - __bfloat162float(h0));
            __nv_bfloat16 l1 = __float2bfloat16(v1 - __bfloat162float(h1));
            hp[c >> 1] = pack_bf2(h0, h1);
            lp[c >> 1] = pack_bf2(l0, l1);
        }
        size_t g = (size_t)grow * N + gcol0;
        *(uint4*)(outh + g)      = make_uint4(hp[0],  hp[1],  hp[2],  hp[3]);
        *(uint4*)(outh + g + 8)  = make_uint4(hp[4],  hp[5],  hp[6],  hp[7]);
        *(uint4*)(outh + g + 16) = make_uint4(hp[8],  hp[9],  hp[10], hp[11]);
        *(uint4*)(outh + g + 24) = make_uint4(hp[12], hp[13], hp[14], hp[15]);
        *(uint4*)(outl + g)      = make_uint4(lp[0],  lp[1],  lp[2],  lp[3]);
        *(uint4*)(outl + g + 8)  = make_uint4(lp[4],  lp[5],  lp[6],  lp[7]);
        *(uint4*)(outl + g + 16) = make_uint4(lp[8],  lp[9],  lp[10], lp[11]);
        *(uint4*)(outl + g + 24) = make_uint4(lp[12], lp[13], lp[14], lp[15]);
    }
}

// ---------------- wmma iteration kernel: 512 threads (unchanged from R14) ----------------
#define IT_BT_H 0
#define IT_BT_L 36864
#define IT_MO_H 73728
#define IT_MO_L 107520
#define IT_ZH   141312
#define IT_ZL   158208
#define IT_TH   175104
#define IT_TL   179712
#define IT_SC   184320
#define IT_SMEM 217600
#define ZB 264
#define TB 72
#define SB 260
#define SC1B_OFF 2304

__device__ __forceinline__ void it_gemm1(const __nv_bfloat16* zh, const __nv_bfloat16* zl,
                                         const __nv_bfloat16* Bh, const __nv_bfloat16* Bl,
                                         float* sc1, int tr, int tc, int kh) {
    wmma::fragment<wmma::accumulator, 16, 16, 16, float> acc;
    wmma::fill_fragment(acc, 0.f);
    #pragma unroll
    for (int k = 0; k < 8; k++) {
        int kk = kh * 8 + k;
        wmma::fragment<wmma::matrix_a, 16, 16, 16, __nv_bfloat16, wmma::row_major> ah, al;
        wmma::fragment<wmma::matrix_b, 16, 16, 16, __nv_bfloat16, wmma::row_major> bh, bl;
        wmma::load_matrix_sync(ah, zh + tr * 16 * ZB + kk * 16, ZB);
        wmma::load_matrix_sync(al, zl + tr * 16 * ZB + kk * 16, ZB);
        wmma::load_matrix_sync(bh, Bh + kk * 16 * TB + tc * 16, TB);
        wmma::load_matrix_sync(bl, Bl + kk * 16 * TB + tc * 16, TB);
        wmma::mma_sync(acc, ah, bh, acc);
        wmma::mma_sync(acc, ah, bl, acc);
        wmma::mma_sync(acc, al, bh, acc);
    }
    wmma::store_matrix_sync(sc1 + tr * 16 * TB + tc * 16, acc, TB, wmma::mem_row_major);
}

__device__ __forceinline__ void it_gemm2(const __nv_bfloat16* th, const __nv_bfloat16* tl,
                                         const __nv_bfloat16* Mh, const __nv_bfloat16* Ml,
                                         float* scf, int tr, int tcol) {
    wmma::fragment<wmma::accumulator, 16, 16, 16, float> acc[2];
    #pragma unroll
    for (int j = 0; j < 2; j++) wmma::fill_fragment(acc[j], 0.f);
    #pragma unroll
    for (int k = 0; k < 4; k++) {
        wmma::fragment<wmma::matrix_a, 16, 16, 16, __nv_bfloat16, wmma::row_major> ah, al;
        wmma::load_matrix_sync(ah, th + tr * 16 * TB + k * 16, TB);
        wmma::load_matrix_sync(al, tl + tr * 16 * TB + k * 16, TB);
        #pragma unroll
        for (int j = 0; j < 2; j++) {
            wmma::fragment<wmma::matrix_b, 16, 16, 16, __nv_bfloat16, wmma::row_major> bh, bl;
            wmma::load_matrix_sync(bh, Mh + k * 16 * ZB + tcol * 32 + j * 16, ZB);
            wmma::load_matrix_sync(bl, Ml + k * 16 * ZB + tcol * 32 + j * 16, ZB);
            wmma::mma_sync(acc[j], ah, bh, acc[j]);
            wmma::mma_sync(acc[j], ah, bl, acc[j]);
            wmma::mma_sync(acc[j], al, bh, acc[j]);
        }
    }
    #pragma unroll
    for (int j = 0; j < 2; j++)
        wmma::store_matrix_sync(scf + tr * 16 * SB + tcol * 32 + j * 16, acc[j], SB, wmma::mem_row_major);
}

__global__ __launch_bounds__(512, 1) void iter_wmma(
    const float* __restrict__ y0g, const float* __restrict__ bcong,
    const float* __restrict__ Ag, float* __restrict__ outg,
    const int* __restrict__ nip) {
    extern __shared__ char smi[];
    __nv_bfloat16* Bt_h = (__nv_bfloat16*)(smi + IT_BT_H);
    __nv_bfloat16* Bt_l = (__nv_bfloat16*)(smi + IT_BT_L);
    __nv_bfloat16* Mo_h = (__nv_bfloat16*)(smi + IT_MO_H);
    __nv_bfloat16* Mo_l = (__nv_bfloat16*)(smi + IT_MO_L);
    __nv_bfloat16* zh   = (__nv_bfloat16*)(smi + IT_ZH);
    __nv_bfloat16* zl   = (__nv_bfloat16*)(smi + IT_ZL);
    __nv_bfloat16* th   = (__nv_bfloat16*)(smi + IT_TH);
    __nv_bfloat16* tl   = (__nv_bfloat16*)(smi + IT_TL);
    float*         scf  = (float*)(smi + IT_SC);
    float*         sc1a = scf;
    float*         sc1b = scf + SC1B_OFF;

    const int tid = threadIdx.x, lane = tid & 31, w = tid >> 5;
    const int g1_tr = w & 1, g1_tc = (w >> 1) & 3, g1_kh = w >> 3;
    const int g2_tr = w & 1, g2_tc = w >> 1;
    const int row0 = blockIdx.x * 32;
    const int wc0 = w * 16;
    const int s_row = tid >> 4, s_m0 = (tid & 15) * 4;
    const int ni = *nip;

    for (int i = tid; i < 64 * 256; i += 512) {
        int m = i >> 8, d = i & 255;
        float v = 0.5f * Ag[i];
        __nv_bfloat16 h = __float2bfloat16(v);
        Bt_h[d * TB + m] = h;
        Bt_l[d * TB + m] = __float2bfloat16(v - __bfloat162float(h));
    }
    for (int i = tid; i < 64 * 256; i += 512) {
        int m = i >> 8, c = i & 255;
        float v = g_Mop[i];
        __nv_bfloat16 h = __float2bfloat16(v);
        Mo_h[m * ZB + c] = h;
        Mo_l[m * ZB + c] = __float2bfloat16(v - __bfloat162float(h));
    }
    float z[16], rv[16];
    #pragma unroll
    for (int j = 0; j < 16; j += 2) {
        float2 v = *(const float2*)(y0g + (size_t)(row0 + lane) * 256 + wc0 + j);
        z[j] = v.x; z[j + 1] = v.y;
        __nv_bfloat16 h0 = __float2bfloat16(v.x), h1 = __float2bfloat16(v.y);
        __nv_bfloat16 l0 = __float2bfloat16(v.x - __bfloat162float(h0));
        __nv_bfloat16 l1 = __float2bfloat16(v.y - __bfloat162float(h1));
        *(uint32_t*)(zh + lane * ZB + wc0 + j) = pack_bf2(h0, h1);
        *(uint32_t*)(zl + lane * ZB + wc0 + j) = pack_bf2(l0, l1);
    }
    __syncthreads();

    it_gemm1(zh, zl, Bt_h, Bt_l, g1_kh ? sc1b : sc1a, g1_tr, g1_tc, g1_kh);
    __syncthreads();
    {
        float4 va = *(const float4*)(sc1a + s_row * TB + s_m0);
        float4 vb = *(const float4*)(sc1b + s_row * TB + s_m0);
        const float* bp = bcong + (size_t)(row0 + s_row) * 64 + s_m0;
        float f[4] = {va.x + vb.x - bp[0], va.y + vb.y - bp[1],
                      va.z + vb.z - bp[2], va.w + vb.w - bp[3]};
        #pragma unroll
        for (int q = 0; q < 4; q += 2) {
            __nv_bfloat16 h0 = __float2bfloat16(f[q]), h1 = __float2bfloat16(f[q + 1]);
            __nv_bfloat16 l0 = __float2bfloat16(f[q]     - __bfloat162float(h0));
            __nv_bfloat16 l1 = __float2bfloat16(f[q + 1] - __bfloat162float(h1));
            *(uint32_t*)(th + s_row * TB + s_m0 + q) = pack_bf2(h0, h1);
            *(uint32_t*)(tl + s_row * TB + s_m0 + q) = pack_bf2(l0, l1);
        }
    }
    __syncthreads();
    it_gemm2(th, tl, Mo_h, Mo_l, scf, g2_tr, g2_tc);
    __syncthreads();
    #pragma unroll
    for (int j = 0; j < 16; j += 2) {
        float2 sv = *(const float2*)(scf + lane * SB + wc0 + j);
        rv[j]     = 0.5f * z[j]     - sv.x;
        rv[j + 1] = 0.5f * z[j + 1] - sv.y;
    }

    for (int it = 0; it < ni; it++) {
        __syncthreads();
        it_gemm1(zh, zl, Bt_h, Bt_l, g1_kh ? sc1b : sc1a, g1_tr, g1_tc, g1_kh);
        __syncthreads();
        {
            float4 va = *(const float4*)(sc1a + s_row * TB + s_m0);
            float4 vb = *(const float4*)(sc1b + s_row * TB + s_m0);
            float f[4] = {va.x + vb.x, va.y + vb.y, va.z + vb.z, va.w + vb.w};
            #pragma unroll
            for (int q = 0; q < 4; q += 2) {
                __nv_bfloat16 h0 = __float2bfloat16(f[q]), h1 = __float2bfloat16(f[q + 1]);
                __nv_bfloat16 l0 = __float2bfloat16(f[q]     - __bfloat162float(h0));
                __nv_bfloat16 l1 = __float2bfloat16(f[q + 1] - __bfloat162float(h1));
                *(uint32_t*)(th + s_row * TB + s_m0 + q) = pack_bf2(h0, h1);
                *(uint32_t*)(tl + s_row * TB + s_m0 + q) = pack_bf2(l0, l1);
            }
        }
        __syncthreads();
        it_gemm2(th, tl, Mo_h, Mo_l, scf, g2_tr, g2_tc);
        __syncthreads();
        if (it == ni - 1) {
            #pragma unroll
            for (int j = 0; j < 16; j += 2) {
                float2 sv = *(const float2*)(scf + lane * SB + wc0 + j);
                float y0v = 0.5f * z[j]     - sv.x + rv[j];
                float y1v = 0.5f * z[j + 1] - sv.y + rv[j + 1];
                *(float2*)(outg + (size_t)(row0 + lane) * 256 + wc0 + j) = make_float2(y0v, y1v);
            }
        } else {
            #pragma unroll
            for (int j = 0; j < 16; j += 2) {
                float2 sv = *(const float2*)(scf + lane * SB + wc0 + j);
                float y0v = 0.5f * z[j]     - sv.x + rv[j];
                float y1v = 0.5f * z[j + 1] - sv.y + rv[j + 1];
                float w0 = fmaxf(2.f * y0v - z[j],     0.f);
                float w1 = fmaxf(2.f * y1v - z[j + 1], 0.f);
                z[j]     += OMEGA * (w0 - y0v);
                z[j + 1] += OMEGA * (w1 - y1v);
                __nv_bfloat16 h0 = __float2bfloat16(z[j]), h1 = __float2bfloat16(z[j + 1]);
                __nv_bfloat16 l0 = __float2bfloat16(z[j]     - __bfloat162float(h0));
                __nv_bfloat16 l1 = __float2bfloat16(z[j + 1] - __bfloat162float(h1));
                *(uint32_t*)(zh + lane * ZB + wc0 + j) = pack_bf2(h0, h1);
                *(uint32_t*)(zl + lane * ZB + wc0 + j) = pack_bf2(l0, l1);
            }
        }
    }
}

// =====================================================================
extern "C" void kernel_launch(void* const* d_in, const int* in_sizes, int n_in,
                              void* d_out, int out_size) {
    const float* x    = (const float*)d_in[0];
    const float* bcon = (const float*)d_in[1];
    const float* A    = (const float*)d_in[2];
    const float* W1   = (const float*)d_in[3];
    const float* b1   = (const float*)d_in[4];
    const float* W2   = (const float*)d_in[5];
    const float* b2   = (const float*)d_in[6];
    const float* W3   = (const float*)d_in[7];
    const float* b3   = (const float*)d_in[8];
    const float* Wout = (const float*)d_in[9];
    const float* bout = (const float*)d_in[10];
    const int*   nip  = (const int*)d_in[11];
    float* out = (float*)d_out;

    cudaFuncSetAttribute(setup_kernel, cudaFuncAttributeMaxDynamicSharedMemorySize, SETUP_SMEM);
    cudaFuncSetAttribute(iter_wmma,    cudaFuncAttributeMaxDynamicSharedMemorySize, IT_SMEM);
    cudaFuncSetAttribute(gemm_wmma2<true, false>, cudaFuncAttributeMaxDynamicSharedMemorySize, GSMEM);
    cudaFuncSetAttribute(gemm_wmma2<false, true>, cudaFuncAttributeMaxDynamicSharedMemorySize, GSMEM);

    void *py0;
    cudaGetSymbolAddress(&py0, g_y0);
    float* y0 = (float*)py0;
    void *pxh, *pxl, *p1h, *p1l, *p2h, *p2l;
    void *pw1h, *pw1l, *pw2h, *pw2l, *pw3h, *pw3l, *pw4h, *pw4l;
    cudaGetSymbolAddress(&pxh, g_xh);   cudaGetSymbolAddress(&pxl, g_xl);
    cudaGetSymbolAddress(&p1h, g_h1h);  cudaGetSymbolAddress(&p1l, g_h1l);
    cudaGetSymbolAddress(&p2h, g_h2h);  cudaGetSymbolAddress(&p2l, g_h2l);
    cudaGetSymbolAddress(&pw1h, g_w1h); cudaGetSymbolAddress(&pw1l, g_w1l);
    cudaGetSymbolAddress(&pw2h, g_w2h); cudaGetSymbolAddress(&pw2l, g_w2l);
    cudaGetSymbolAddress(&pw3h, g_w3h); cudaGetSymbolAddress(&pw3l, g_w3l);
    cudaGetSymbolAddress(&pw4h, g_w4h); cudaGetSymbolAddress(&pw4l, g_w4l);
    __nv_bfloat16 *xh = (__nv_bfloat16*)pxh, *xl = (__nv_bfloat16*)pxl;
    __nv_bfloat16 *h1h = (__nv_bfloat16*)p1h, *h1l = (__nv_bfloat16*)p1l;
    __nv_bfloat16 *h2h = (__nv_bfloat16*)p2h, *h2l = (__nv_bfloat16*)p2l;
    __nv_bfloat16 *w1h = (__nv_bfloat16*)pw1h, *w1l = (__nv_bfloat16*)pw1l;
    __nv_bfloat16 *w2h = (__nv_bfloat16*)pw2h, *w2l = (__nv_bfloat16*)pw2l;
    __nv_bfloat16 *w3h = (__nv_bfloat16*)pw3h, *w3l = (__nv_bfloat16*)pw3l;
    __nv_bfloat16 *w4h = (__nv_bfloat16*)pw4h, *w4l = (__nv_bfloat16*)pw4l;

    cvt_split<<<(4096 * 128 + 255) / 256, 256>>>(x, xh, xl, 4096 * 128);
    cvt_split<<<(128 * 512 + 255) / 256, 256>>>(W1, w1h, w1l, 128 * 512);
    cvt_split<<<(512 * 512 + 255) / 256, 256>>>(W2, w2h, w2l, 512 * 512);
    cvt_split<<<(512 * 512 + 255) / 256, 256>>>(W3, w3h, w3l, 512 * 512);
    cvt_split<<<(512 * 256 + 255) / 256, 256>>>(Wout, w4h, w4l, 512 * 256);
    setup_kernel<<<1, 256, SETUP_SMEM>>>(A);

    gemm_wmma2<true, false><<<dim3(4, 32), 512, GSMEM>>>(xh, xl, w1h, w1l, b1, nullptr, h1h, h1l, 4096, 512, 128);
    gemm_wmma2<true, false><<<dim3(4, 32), 512, GSMEM>>>(h1h, h1l, w2h, w2l, b2, nullptr, h2h, h2l, 4096, 512, 512);
    gemm_wmma2<true, false><<<dim3(4, 32), 512, GSMEM>>>(h2h, h2l, w3h, w3l, b3, nullptr, h1h, h1l, 4096, 512, 512);
    gemm_wmma2<false, true><<<dim3(2, 32), 512, GSMEM>>>(h1h, h1l, w4h, w4l, bout, y0, nullptr, nullptr, 4096, 256, 512);

    iter_wmma<<<128, 512, IT_SMEM>>>(y0, bcon, A, out, nip);
}